// round 8
// baseline (speedup 1.0000x reference)
#include <cuda_runtime.h>
#include <cuda_fp16.h>
#include <math.h>
#include <stdint.h>

#define SEQ   2048
#define HID   2048
#define NH    16
#define DK    64
#define DV    128
#define KEYD  1024
#define VALD  2048
#define CDIM  4096   // 2*KEYD + VALD
#define NSEG  2
#define SEGR  (SEQ / NSEG)   // 1024 rows per segment

// ------------------------------------------------------------------
// Scratch (device globals; no allocation allowed)
// ------------------------------------------------------------------
__device__ float  g_mixed[SEQ * CDIM];
__device__ float  g_qkv  [SEQ * CDIM];   // post conv+silu (q | k | v)
__device__ float2 g_eb   [SEQ * NH];     // (exp(g), beta)
__device__ float  g_z    [SEQ * VALD];
__device__ float  g_core [SEQ * VALD];
__device__ float  g_state[NH * DV * DK]; // scan state between segments

__device__ __half g_hs_h  [SEQ  * HID];
__device__ __half g_Wqkv_h[CDIM * HID];
__device__ __half g_Wz_h  [VALD * HID];
__device__ __half g_Wout_h[HID  * VALD];
__device__ __half g_gat_h [SEQ  * VALD];

// ------------------------------------------------------------------
// PTX helpers (base ISA: cp.async / ldmatrix / mma.sync)
// ------------------------------------------------------------------
__device__ __forceinline__ uint32_t smem_u32(const void* p) {
    uint32_t a;
    asm("{ .reg .u64 t; cvta.to.shared.u64 t, %1; cvt.u32.u64 %0, t; }"
        : "=r"(a) : "l"(p));
    return a;
}
__device__ __forceinline__ void cp_async16(uint32_t s, const void* g) {
    asm volatile("cp.async.cg.shared.global [%0], [%1], 16;" :: "r"(s), "l"(g));
}
__device__ __forceinline__ void cp_async8(uint32_t s, const void* g) {
    asm volatile("cp.async.ca.shared.global [%0], [%1], 8;" :: "r"(s), "l"(g));
}
__device__ __forceinline__ void cp_commit() {
    asm volatile("cp.async.commit_group;");
}
template <int N>
__device__ __forceinline__ void cp_wait() {
    asm volatile("cp.async.wait_group %0;" :: "n"(N));
}
__device__ __forceinline__ void ldsm4(uint32_t& r0, uint32_t& r1,
                                      uint32_t& r2, uint32_t& r3, uint32_t a) {
    asm volatile("ldmatrix.sync.aligned.m8n8.x4.shared.b16 {%0,%1,%2,%3}, [%4];"
                 : "=r"(r0), "=r"(r1), "=r"(r2), "=r"(r3) : "r"(a));
}
__device__ __forceinline__ void mma16816(float* d, const uint32_t* a,
                                         uint32_t b0, uint32_t b1) {
    asm volatile(
        "mma.sync.aligned.m16n8k16.row.col.f32.f16.f16.f32 "
        "{%0,%1,%2,%3}, {%4,%5,%6,%7}, {%8,%9}, {%0,%1,%2,%3};"
        : "+f"(d[0]), "+f"(d[1]), "+f"(d[2]), "+f"(d[3])
        : "r"(a[0]), "r"(a[1]), "r"(a[2]), "r"(a[3]), "r"(b0), "r"(b1));
}
#define SW(off) ((off) ^ (((off) >> 3) & 0x70))

// ------------------------------------------------------------------
// fp16 NT GEMM via mma.sync: C[M,N] = A[M,K] * B[N,K]^T (fp32 out)
// BM=BN=128, BK=64, 256 threads (8 warps, 4x2), double-buffered cp.async.
// ------------------------------------------------------------------
#define HGEMM_SMEM (4 * 16384)

__global__ __launch_bounds__(256)
void hgemm_nt(const __half* __restrict__ A, const __half* __restrict__ B,
              float* __restrict__ C, int M, int N, int K)
{
    extern __shared__ __align__(1024) char sm[];
    const int tid  = threadIdx.x;
    const int wid  = tid >> 5, lane = tid & 31;
    const int tileN = blockIdx.x, tileM = blockIdx.y;
    const int wm = (wid >> 1) * 32;
    const int wn = (wid & 1) * 64;

    const uint32_t sbase = smem_u32(sm);

    const char* Ag = (const char*)(A + (size_t)tileM * 128 * K);
    const char* Bg = (const char*)(B + (size_t)tileN * 128 * K);
    const size_t rs = (size_t)K * 2;

    const int crow = tid >> 3;
    const int ccol = (tid & 7) * 16;

    int offA[2], offB[4];
#pragma unroll
    for (int mt = 0; mt < 2; mt++)
        offA[mt] = (wm + mt * 16 + (lane & 15)) * 128 + (lane >> 4) * 16;
#pragma unroll
    for (int j2 = 0; j2 < 4; j2++)
        offB[j2] = (wn + j2 * 16 + (lane & 7) + ((lane >> 4) & 1) * 8) * 128
                 + ((lane >> 3) & 1) * 16;

    float acc[2][8][4];
#pragma unroll
    for (int mt = 0; mt < 2; mt++)
#pragma unroll
        for (int nt = 0; nt < 8; nt++)
#pragma unroll
            for (int r = 0; r < 4; r++) acc[mt][nt][r] = 0.f;

    const int chunks = K >> 6;

#define ISSUEG(i, b)                                                         \
    do {                                                                     \
        uint32_t sA = sbase + (b) * 32768;                                   \
        uint32_t sB = sA + 16384;                                            \
        const char* gA = Ag + (size_t)(i) * 128 + ccol;                      \
        const char* gB = Bg + (size_t)(i) * 128 + ccol;                      \
        _Pragma("unroll")                                                    \
        for (int p = 0; p < 4; p++) {                                        \
            int row = crow + p * 32;                                         \
            int so  = SW(row * 128 + ccol);                                  \
            cp_async16(sA + so, gA + row * rs);                              \
            cp_async16(sB + so, gB + row * rs);                              \
        }                                                                    \
        cp_commit();                                                         \
    } while (0)

    ISSUEG(0, 0);

    for (int i = 0; i < chunks; i++) {
        const int b = i & 1;
        if (i + 1 < chunks) { ISSUEG(i + 1, b ^ 1); cp_wait<1>(); }
        else                { cp_wait<0>(); }
        __syncthreads();

        const uint32_t sA = sbase + b * 32768;
        const uint32_t sB = sA + 16384;
#pragma unroll
        for (int ks = 0; ks < 4; ks++) {
            uint32_t af[2][4];
#pragma unroll
            for (int mt = 0; mt < 2; mt++) {
                int off = offA[mt] + ks * 32;
                ldsm4(af[mt][0], af[mt][1], af[mt][2], af[mt][3], sA + SW(off));
            }
            uint32_t bf[8][2];
#pragma unroll
            for (int j2 = 0; j2 < 4; j2++) {
                int off = offB[j2] + ks * 32;
                uint32_t r0, r1, r2, r3;
                ldsm4(r0, r1, r2, r3, sB + SW(off));
                bf[2 * j2][0] = r0; bf[2 * j2][1] = r1;
                bf[2 * j2 + 1][0] = r2; bf[2 * j2 + 1][1] = r3;
            }
#pragma unroll
            for (int mt = 0; mt < 2; mt++)
#pragma unroll
                for (int nt = 0; nt < 8; nt++)
                    mma16816(acc[mt][nt], af[mt], bf[nt][0], bf[nt][1]);
        }
        __syncthreads();
    }
#undef ISSUEG

    const int gid = lane >> 2, ctg = lane & 3;
#pragma unroll
    for (int mt = 0; mt < 2; mt++) {
        int m0 = tileM * 128 + wm + mt * 16 + gid;
#pragma unroll
        for (int nt = 0; nt < 8; nt++) {
            int n0 = tileN * 128 + wn + nt * 8 + ctg * 2;
            *(float2*)(C + (size_t)m0 * N + n0) =
                make_float2(acc[mt][nt][0], acc[mt][nt][1]);
            *(float2*)(C + (size_t)(m0 + 8) * N + n0) =
                make_float2(acc[mt][nt][2], acc[mt][nt][3]);
        }
    }
}

// ------------------------------------------------------------------
// fp32 -> fp16 conversion, 8 elems/thread.
// ------------------------------------------------------------------
__global__ __launch_bounds__(256)
void f2h_kernel(const float* __restrict__ in, __half* __restrict__ out)
{
    int idx = (blockIdx.x * 256 + threadIdx.x) * 8;
    float4 x0 = *(const float4*)(in + idx);
    float4 x1 = *(const float4*)(in + idx + 4);
    union { __half2 h[4]; uint4 u; } r;
    r.h[0] = __floats2half2_rn(x0.x, x0.y);
    r.h[1] = __floats2half2_rn(x0.z, x0.w);
    r.h[2] = __floats2half2_rn(x1.x, x1.y);
    r.h[3] = __floats2half2_rn(x1.z, x1.w);
    *(uint4*)(out + idx) = r.u;
}

// ------------------------------------------------------------------
// Fused conv(K=4)+SiLU+l2norm over one row segment.
// One block per row t. 512 threads, 8 channels each.
// q/k heads are 64 channels = 8 consecutive lanes -> shfl-group norm.
// ------------------------------------------------------------------
__global__ __launch_bounds__(512)
void conv_norm_seg(const float* __restrict__ mixed,
                   const float* __restrict__ w,
                   float* __restrict__ qkv, int row0)
{
    const int t  = row0 + blockIdx.x;
    const int c0 = threadIdx.x * 8;
    const size_t idx = (size_t)t * CDIM + c0;

    float x[8];
    {
        float4 a0 = *(const float4*)(mixed + idx);
        float4 a1 = *(const float4*)(mixed + idx + 4);
        float xs[8] = {a0.x, a0.y, a0.z, a0.w, a1.x, a1.y, a1.z, a1.w};
        float p1[8] = {0}, p2[8] = {0}, p3[8] = {0};
        if (t >= 1) {
            float4 b0 = *(const float4*)(mixed + idx - CDIM);
            float4 b1 = *(const float4*)(mixed + idx - CDIM + 4);
            p1[0]=b0.x;p1[1]=b0.y;p1[2]=b0.z;p1[3]=b0.w;p1[4]=b1.x;p1[5]=b1.y;p1[6]=b1.z;p1[7]=b1.w;
        }
        if (t >= 2) {
            float4 b0 = *(const float4*)(mixed + idx - 2 * CDIM);
            float4 b1 = *(const float4*)(mixed + idx - 2 * CDIM + 4);
            p2[0]=b0.x;p2[1]=b0.y;p2[2]=b0.z;p2[3]=b0.w;p2[4]=b1.x;p2[5]=b1.y;p2[6]=b1.z;p2[7]=b1.w;
        }
        if (t >= 3) {
            float4 b0 = *(const float4*)(mixed + idx - 3 * CDIM);
            float4 b1 = *(const float4*)(mixed + idx - 3 * CDIM + 4);
            p3[0]=b0.x;p3[1]=b0.y;p3[2]=b0.z;p3[3]=b0.w;p3[4]=b1.x;p3[5]=b1.y;p3[6]=b1.z;p3[7]=b1.w;
        }
#pragma unroll
        for (int j = 0; j < 8; j++) {
            float4 wj = *(const float4*)(w + (c0 + j) * 4);
            float acc = wj.w * xs[j];
            acc = fmaf(wj.z, p1[j], acc);
            acc = fmaf(wj.y, p2[j], acc);
            acc = fmaf(wj.x, p3[j], acc);
            x[j] = acc / (1.f + expf(-acc));   // silu
        }
    }

    if (c0 < 2 * KEYD) {
        // q or k: l2-normalize per 64-channel head (8-lane group)
        float ss = 0.f;
#pragma unroll
        for (int j = 0; j < 8; j++) ss += x[j] * x[j];
        ss += __shfl_xor_sync(0xffffffffu, ss, 1);
        ss += __shfl_xor_sync(0xffffffffu, ss, 2);
        ss += __shfl_xor_sync(0xffffffffu, ss, 4);
        float r = rsqrtf(ss + 1e-6f);
        if (c0 < KEYD) r *= 0.125f;   // q scale 1/sqrt(64)
#pragma unroll
        for (int j = 0; j < 8; j++) x[j] *= r;
    }
    float4 o0 = make_float4(x[0], x[1], x[2], x[3]);
    float4 o1 = make_float4(x[4], x[5], x[6], x[7]);
    *(float4*)(qkv + idx)     = o0;
    *(float4*)(qkv + idx + 4) = o1;
}

// ------------------------------------------------------------------
// a/b projections -> (exp(g), beta) float2. One warp per (t,h).
// ------------------------------------------------------------------
__global__ __launch_bounds__(256)
void ab_kernel(const float* __restrict__ hs,
               const float* __restrict__ Wa,
               const float* __restrict__ Wb,
               const float* __restrict__ A_log,
               const float* __restrict__ dt_bias,
               float2* __restrict__ eb)
{
    int w    = blockIdx.x * (blockDim.x >> 5) + (threadIdx.x >> 5);
    int lane = threadIdx.x & 31;
    if (w >= SEQ * NH) return;
    int t = w >> 4, h = w & 15;

    const float4* x4 = (const float4*)(hs + (size_t)t * HID);
    const float4* a4 = (const float4*)(Wa + (size_t)h * HID);
    const float4* b4 = (const float4*)(Wb + (size_t)h * HID);

    float sa = 0.f, sb = 0.f;
    for (int i = lane; i < HID / 4; i += 32) {
        float4 x = x4[i], a = a4[i], b = b4[i];
        sa += x.x * a.x + x.y * a.y + x.z * a.z + x.w * a.w;
        sb += x.x * b.x + x.y * b.y + x.z * b.z + x.w * b.w;
    }
#pragma unroll
    for (int o = 16; o; o >>= 1) {
        sa += __shfl_xor_sync(0xffffffffu, sa, o);
        sb += __shfl_xor_sync(0xffffffffu, sb, o);
    }
    if (lane == 0) {
        float av = sa + dt_bias[h];
        float sp = (av > 20.f) ? av : log1pf(expf(av));
        eb[t * NH + h] = make_float2(expf(-expf(A_log[h]) * sp),
                                     1.f / (1.f + expf(-sb)));
    }
}

// ------------------------------------------------------------------
// Delta-rule scan SEGMENT [t0, tend). Warp-autonomous.
// cp.async smem ring, depth 8 (t0 must be a multiple of 8).
// 256 single-warp blocks: (head h = bid>>4, vgroup = bid&15).
// lane: qtr = lane&3 (16 of DK), vl = lane>>2 (8 v's per warp).
// Ring slot (576B): [0:256) k, [256:512) q, [512:544) v8, [544:552) eb.
// ------------------------------------------------------------------
__global__ __launch_bounds__(32)
void scan_seg(const float* __restrict__ qkv,
              const float2* __restrict__ eb_arr,
              float* __restrict__ core,
              float* __restrict__ state,
              int t0, int tend)
{
    const int h    = blockIdx.x >> 4;
    const int vg   = blockIdx.x & 15;
    const int lane = threadIdx.x;
    const int qtr  = lane & 3;
    const int vl   = lane >> 2;
    const int v    = vg * 8 + vl;

    __shared__ __align__(16) float ring[8][144];
    const uint32_t rb = smem_u32(ring);

    float* sp = state + ((size_t)(h * DV + v)) * DK + qtr * 16;

    float S[16];
    if (t0 == 0) {
#pragma unroll
        for (int i = 0; i < 16; i++) S[i] = 0.f;
    } else {
#pragma unroll
        for (int i = 0; i < 4; i++) {
            float4 s4 = ((const float4*)sp)[i];
            S[4 * i + 0] = s4.x; S[4 * i + 1] = s4.y;
            S[4 * i + 2] = s4.z; S[4 * i + 3] = s4.w;
        }
    }

#define ISSUE(tt)                                                          \
    do {                                                                   \
        int _t = (tt); if (_t >= SEQ) _t = SEQ - 1;                        \
        uint32_t _s = rb + (uint32_t)(_t & 7) * 576;                       \
        size_t _o = (size_t)_t * CDIM;                                     \
        if (lane < 16)                                                     \
            cp_async16(_s + lane * 16, qkv + _o + KEYD + h * DK + lane * 4); \
        else                                                               \
            cp_async16(_s + 256 + (lane - 16) * 16,                        \
                       qkv + _o + h * DK + (lane - 16) * 4);               \
        if (lane < 2)                                                      \
            cp_async16(_s + 512 + lane * 16,                               \
                       qkv + _o + 2 * KEYD + h * DV + vg * 8 + lane * 4);  \
        if (lane == 2)                                                     \
            cp_async8(_s + 544, eb_arr + _t * NH + h);                     \
        cp_commit();                                                       \
    } while (0)

    float4 kf[4], qf[4];
    float  vt, eg, bt;

#define LDSSTEP(tt)                                                        \
    do {                                                                   \
        const float* _b = ring[(tt) & 7];                                  \
        const float4* _k4 = (const float4*)(_b + qtr * 16);                \
        const float4* _q4 = (const float4*)(_b + 64 + qtr * 16);           \
        kf[0] = _k4[0]; kf[1] = _k4[1]; kf[2] = _k4[2]; kf[3] = _k4[3];    \
        qf[0] = _q4[0]; qf[1] = _q4[1]; qf[2] = _q4[2]; qf[3] = _q4[3];    \
        vt = _b[128 + vl];                                                 \
        float2 _e = *(const float2*)(_b + 136);                            \
        eg = _e.x; bt = _e.y;                                              \
    } while (0)

    for (int tt = t0; tt < t0 + 8; tt++) ISSUE(tt);
    cp_wait<7>();
    __syncwarp();
    LDSSTEP(t0);

    for (int t = t0; t < tend; t++) {
        ISSUE(t + 8);

        // --- compute step t (regs already loaded) ---
        float r0 = 0.f, r1 = 0.f, r2 = 0.f, r3 = 0.f;
#pragma unroll
        for (int j = 0; j < 4; j++) {
            r0 = fmaf(kf[j].x, S[4 * j + 0], r0);
            r1 = fmaf(kf[j].y, S[4 * j + 1], r1);
            r2 = fmaf(kf[j].z, S[4 * j + 2], r2);
            r3 = fmaf(kf[j].w, S[4 * j + 3], r3);
        }
        float raw = (r0 + r1) + (r2 + r3);
        raw += __shfl_xor_sync(0xffffffffu, raw, 1);
        raw += __shfl_xor_sync(0xffffffffu, raw, 2);

        float dl = (vt - eg * raw) * bt;

        float o0 = 0.f, o1 = 0.f, o2 = 0.f, o3 = 0.f;
#pragma unroll
        for (int j = 0; j < 4; j++) {
            float s0 = fmaf(S[4 * j + 0], eg, kf[j].x * dl);
            float s1 = fmaf(S[4 * j + 1], eg, kf[j].y * dl);
            float s2 = fmaf(S[4 * j + 2], eg, kf[j].z * dl);
            float s3 = fmaf(S[4 * j + 3], eg, kf[j].w * dl);
            S[4 * j + 0] = s0; S[4 * j + 1] = s1;
            S[4 * j + 2] = s2; S[4 * j + 3] = s3;
            o0 = fmaf(qf[j].x, s0, o0);
            o1 = fmaf(qf[j].y, s1, o1);
            o2 = fmaf(qf[j].z, s2, o2);
            o3 = fmaf(qf[j].w, s3, o3);
        }
        float o = (o0 + o1) + (o2 + o3);
        o += __shfl_xor_sync(0xffffffffu, o, 1);
        o += __shfl_xor_sync(0xffffffffu, o, 2);
        if (qtr == 0)
            core[(size_t)t * VALD + h * DV + v] = o;

        // --- stage regs for t+1 ---
        cp_wait<7>();
        __syncwarp();
        if (t + 1 < tend) LDSSTEP(t + 1);
    }
#undef ISSUE
#undef LDSSTEP

#pragma unroll
    for (int i = 0; i < 4; i++)
        ((float4*)sp)[i] = make_float4(S[4 * i + 0], S[4 * i + 1],
                                       S[4 * i + 2], S[4 * i + 3]);
}

// ------------------------------------------------------------------
// Gated RMSNorm + SiLU(z), fp16 output, over one row segment.
// ------------------------------------------------------------------
__global__ __launch_bounds__(256)
void gate_norm_seg(const float* __restrict__ core,
                   const float* __restrict__ z,
                   const float* __restrict__ norm_w,
                   __half* __restrict__ out, int w0)
{
    int w    = w0 + blockIdx.x * (blockDim.x >> 5) + (threadIdx.x >> 5);
    int lane = threadIdx.x & 31;
    int t = w >> 4, h = w & 15;
    size_t base = (size_t)t * VALD + h * DV;

    float4 cv = ((const float4*)(core + base))[lane];
    float ss = cv.x * cv.x + cv.y * cv.y + cv.z * cv.z + cv.w * cv.w;
#pragma unroll
    for (int o = 16; o; o >>= 1) ss += __shfl_xor_sync(0xffffffffu, ss, o);
    float r = rsqrtf(ss * (1.f / DV) + 1e-6f);

    float4 zv = ((const float4*)(z + base))[lane];
    float4 nw = ((const float4*)norm_w)[lane];
    float v0 = cv.x * r * nw.x * (zv.x / (1.f + expf(-zv.x)));
    float v1 = cv.y * r * nw.y * (zv.y / (1.f + expf(-zv.y)));
    float v2 = cv.z * r * nw.z * (zv.z / (1.f + expf(-zv.z)));
    float v3 = cv.w * r * nw.w * (zv.w / (1.f + expf(-zv.w)));

    union { __half2 h[2]; uint2 u; } o2;
    o2.h[0] = __floats2half2_rn(v0, v1);
    o2.h[1] = __floats2half2_rn(v2, v3);
    *(uint2*)(out + base + lane * 4) = o2.u;
}

// ------------------------------------------------------------------
// Launch: 3-stream pipeline over 2 row segments (small graph).
// ------------------------------------------------------------------
static cudaStream_t g_sS = nullptr, g_sT = nullptr;
static cudaEvent_t  g_evFork, g_evHs, g_evAB, g_evEnd;
static cudaEvent_t  g_evQ[NSEG], g_evS[NSEG];

extern "C" void kernel_launch(void* const* d_in, const int* in_sizes, int n_in,
                              void* d_out, int out_size)
{
    const float* hs      = (const float*)d_in[0];
    const float* Wqkv    = (const float*)d_in[1];
    const float* Wa      = (const float*)d_in[2];
    const float* Wb      = (const float*)d_in[3];
    const float* Wz      = (const float*)d_in[4];
    const float* convw   = (const float*)d_in[5];
    const float* A_log   = (const float*)d_in[6];
    const float* dt_bias = (const float*)d_in[7];
    const float* norm_w  = (const float*)d_in[8];
    const float* Wout    = (const float*)d_in[9];
    float* out = (float*)d_out;

    if (!g_sS) {
        cudaStreamCreateWithFlags(&g_sS, cudaStreamNonBlocking);
        cudaStreamCreateWithFlags(&g_sT, cudaStreamNonBlocking);
        cudaEventCreateWithFlags(&g_evFork, cudaEventDisableTiming);
        cudaEventCreateWithFlags(&g_evHs,   cudaEventDisableTiming);
        cudaEventCreateWithFlags(&g_evAB,   cudaEventDisableTiming);
        cudaEventCreateWithFlags(&g_evEnd,  cudaEventDisableTiming);
        for (int b = 0; b < NSEG; b++) {
            cudaEventCreateWithFlags(&g_evQ[b], cudaEventDisableTiming);
            cudaEventCreateWithFlags(&g_evS[b], cudaEventDisableTiming);
        }
        cudaFuncSetAttribute(hgemm_nt,
                             cudaFuncAttributeMaxDynamicSharedMemorySize, HGEMM_SMEM);
    }

    float  *p_mixed, *p_qkv, *p_z, *p_core, *p_state;
    float2 *p_eb;
    __half *p_hs, *p_Wqkv, *p_Wz, *p_Wout, *p_gat;
    cudaGetSymbolAddress((void**)&p_mixed, g_mixed);
    cudaGetSymbolAddress((void**)&p_qkv,   g_qkv);
    cudaGetSymbolAddress((void**)&p_eb,    g_eb);
    cudaGetSymbolAddress((void**)&p_z,     g_z);
    cudaGetSymbolAddress((void**)&p_core,  g_core);
    cudaGetSymbolAddress((void**)&p_state, g_state);
    cudaGetSymbolAddress((void**)&p_hs,    g_hs_h);
    cudaGetSymbolAddress((void**)&p_Wqkv,  g_Wqkv_h);
    cudaGetSymbolAddress((void**)&p_Wz,    g_Wz_h);
    cudaGetSymbolAddress((void**)&p_Wout,  g_Wout_h);
    cudaGetSymbolAddress((void**)&p_gat,   g_gat_h);

    cudaEventRecord(g_evFork, 0);
    cudaStreamWaitEvent(g_sS, g_evFork, 0);
    cudaStreamWaitEvent(g_sT, g_evFork, 0);

    // ---- stream 0: conversions + segmented qkv GEMM + conv/norm ----
    f2h_kernel<<<(SEQ * HID / 8) / 256, 256>>>(hs, p_hs);
    cudaEventRecord(g_evHs, 0);
    f2h_kernel<<<(CDIM * HID / 8) / 256, 256>>>(Wqkv, p_Wqkv);

    for (int b = 0; b < NSEG; b++) {
        int row0 = b * SEGR;
        hgemm_nt<<<dim3(CDIM / 128, SEGR / 128), 256, HGEMM_SMEM>>>(
            p_hs + (size_t)row0 * HID, p_Wqkv,
            p_mixed + (size_t)row0 * CDIM, SEGR, CDIM, HID);
        conv_norm_seg<<<SEGR, 512>>>(p_mixed, convw, p_qkv, row0);
        cudaEventRecord(g_evQ[b], 0);
    }

    // ---- stream T: ab, z chain, Wout conversion ----
    ab_kernel<<<(SEQ * NH) / 8, 256, 0, g_sT>>>(hs, Wa, Wb, A_log, dt_bias, p_eb);
    cudaEventRecord(g_evAB, g_sT);
    f2h_kernel<<<(VALD * HID / 8) / 256, 256, 0, g_sT>>>(Wz, p_Wz);
    cudaStreamWaitEvent(g_sT, g_evHs, 0);
    hgemm_nt<<<dim3(VALD / 128, SEQ / 128), 256, HGEMM_SMEM, g_sT>>>(
        p_hs, p_Wz, p_z, SEQ, VALD, HID);
    f2h_kernel<<<(HID * VALD / 8) / 256, 256, 0, g_sT>>>(Wout, p_Wout);

    // ---- stream S: chained scan segments ----
    cudaStreamWaitEvent(g_sS, g_evAB, 0);
    for (int b = 0; b < NSEG; b++) {
        cudaStreamWaitEvent(g_sS, g_evQ[b], 0);
        scan_seg<<<256, 32, 0, g_sS>>>(p_qkv, p_eb, p_core, p_state,
                                       b * SEGR, (b + 1) * SEGR);
        cudaEventRecord(g_evS[b], g_sS);
    }

    // ---- stream T: gate + out GEMM per segment ----
    for (int b = 0; b < NSEG; b++) {
        int row0 = b * SEGR;
        cudaStreamWaitEvent(g_sT, g_evS[b], 0);
        gate_norm_seg<<<(SEGR * NH) / 8, 256, 0, g_sT>>>(
            p_core, p_z, norm_w, p_gat, row0 * NH);
        hgemm_nt<<<dim3(HID / 128, SEGR / 128), 256, HGEMM_SMEM, g_sT>>>(
            p_gat + (size_t)row0 * VALD, p_Wout,
            out + (size_t)row0 * HID, SEGR, HID, VALD);
    }
    cudaEventRecord(g_evEnd, g_sT);
    cudaStreamWaitEvent(0, g_evEnd, 0);
}

// round 9
// speedup vs baseline: 2.6878x; 2.6878x over previous
#include <cuda_runtime.h>
#include <cuda_fp16.h>
#include <math.h>
#include <stdint.h>

#define SEQ   2048
#define HID   2048
#define NH    16
#define DK    64
#define DV    128
#define KEYD  1024
#define VALD  2048
#define CDIM  4096   // 2*KEYD + VALD
#define NSEG  2
#define SEGR  (SEQ / NSEG)   // 1024 rows per segment

// ------------------------------------------------------------------
// Scratch (device globals; no allocation allowed)
// ------------------------------------------------------------------
__device__ float  g_mixed[SEQ * CDIM];
__device__ float  g_qkv  [SEQ * CDIM];   // post conv+silu (q | k | v)
__device__ float2 g_eb   [SEQ * NH];     // (exp(g), beta)
__device__ float  g_z    [SEQ * VALD];
__device__ float  g_core [SEQ * VALD];
__device__ float  g_state[NH * DV * DK]; // scan state between segments

__device__ __half g_hs_h  [SEQ  * HID];
__device__ __half g_Wqkv_h[CDIM * HID];
__device__ __half g_Wz_h  [VALD * HID];
__device__ __half g_Wout_h[HID  * VALD];
__device__ __half g_gat_h [SEQ  * VALD];

// ------------------------------------------------------------------
// PTX helpers (base ISA: cp.async / ldmatrix / mma.sync)
// ------------------------------------------------------------------
__device__ __forceinline__ uint32_t smem_u32(const void* p) {
    uint32_t a;
    asm("{ .reg .u64 t; cvta.to.shared.u64 t, %1; cvt.u32.u64 %0, t; }"
        : "=r"(a) : "l"(p));
    return a;
}
__device__ __forceinline__ void cp_async16(uint32_t s, const void* g) {
    asm volatile("cp.async.cg.shared.global [%0], [%1], 16;" :: "r"(s), "l"(g));
}
__device__ __forceinline__ void cp_commit() {
    asm volatile("cp.async.commit_group;");
}
template <int N>
__device__ __forceinline__ void cp_wait() {
    asm volatile("cp.async.wait_group %0;" :: "n"(N));
}
__device__ __forceinline__ void ldsm4(uint32_t& r0, uint32_t& r1,
                                      uint32_t& r2, uint32_t& r3, uint32_t a) {
    asm volatile("ldmatrix.sync.aligned.m8n8.x4.shared.b16 {%0,%1,%2,%3}, [%4];"
                 : "=r"(r0), "=r"(r1), "=r"(r2), "=r"(r3) : "r"(a));
}
__device__ __forceinline__ void mma16816(float* d, const uint32_t* a,
                                         uint32_t b0, uint32_t b1) {
    asm volatile(
        "mma.sync.aligned.m16n8k16.row.col.f32.f16.f16.f32 "
        "{%0,%1,%2,%3}, {%4,%5,%6,%7}, {%8,%9}, {%0,%1,%2,%3};"
        : "+f"(d[0]), "+f"(d[1]), "+f"(d[2]), "+f"(d[3])
        : "r"(a[0]), "r"(a[1]), "r"(a[2]), "r"(a[3]), "r"(b0), "r"(b1));
}
#define SW(off) ((off) ^ (((off) >> 3) & 0x70))

// ------------------------------------------------------------------
// fp16 NT GEMM via mma.sync: C[M,N] = A[M,K] * B[N,K]^T (fp32 out)
// BM=BN=128, BK=64, 256 threads (8 warps, 4x2), double-buffered cp.async.
// ------------------------------------------------------------------
#define HGEMM_SMEM (4 * 16384)

__global__ __launch_bounds__(256)
void hgemm_nt(const __half* __restrict__ A, const __half* __restrict__ B,
              float* __restrict__ C, int M, int N, int K)
{
    extern __shared__ __align__(1024) char sm[];
    const int tid  = threadIdx.x;
    const int wid  = tid >> 5, lane = tid & 31;
    const int tileN = blockIdx.x, tileM = blockIdx.y;
    const int wm = (wid >> 1) * 32;
    const int wn = (wid & 1) * 64;

    const uint32_t sbase = smem_u32(sm);

    const char* Ag = (const char*)(A + (size_t)tileM * 128 * K);
    const char* Bg = (const char*)(B + (size_t)tileN * 128 * K);
    const size_t rs = (size_t)K * 2;

    const int crow = tid >> 3;
    const int ccol = (tid & 7) * 16;

    int offA[2], offB[4];
#pragma unroll
    for (int mt = 0; mt < 2; mt++)
        offA[mt] = (wm + mt * 16 + (lane & 15)) * 128 + (lane >> 4) * 16;
#pragma unroll
    for (int j2 = 0; j2 < 4; j2++)
        offB[j2] = (wn + j2 * 16 + (lane & 7) + ((lane >> 4) & 1) * 8) * 128
                 + ((lane >> 3) & 1) * 16;

    float acc[2][8][4];
#pragma unroll
    for (int mt = 0; mt < 2; mt++)
#pragma unroll
        for (int nt = 0; nt < 8; nt++)
#pragma unroll
            for (int r = 0; r < 4; r++) acc[mt][nt][r] = 0.f;

    const int chunks = K >> 6;

#define ISSUEG(i, b)                                                         \
    do {                                                                     \
        uint32_t sA = sbase + (b) * 32768;                                   \
        uint32_t sB = sA + 16384;                                            \
        const char* gA = Ag + (size_t)(i) * 128 + ccol;                      \
        const char* gB = Bg + (size_t)(i) * 128 + ccol;                      \
        _Pragma("unroll")                                                    \
        for (int p = 0; p < 4; p++) {                                        \
            int row = crow + p * 32;                                         \
            int so  = SW(row * 128 + ccol);                                  \
            cp_async16(sA + so, gA + row * rs);                              \
            cp_async16(sB + so, gB + row * rs);                              \
        }                                                                    \
        cp_commit();                                                         \
    } while (0)

    ISSUEG(0, 0);

    for (int i = 0; i < chunks; i++) {
        const int b = i & 1;
        if (i + 1 < chunks) { ISSUEG(i + 1, b ^ 1); cp_wait<1>(); }
        else                { cp_wait<0>(); }
        __syncthreads();

        const uint32_t sA = sbase + b * 32768;
        const uint32_t sB = sA + 16384;
#pragma unroll
        for (int ks = 0; ks < 4; ks++) {
            uint32_t af[2][4];
#pragma unroll
            for (int mt = 0; mt < 2; mt++) {
                int off = offA[mt] + ks * 32;
                ldsm4(af[mt][0], af[mt][1], af[mt][2], af[mt][3], sA + SW(off));
            }
            uint32_t bf[8][2];
#pragma unroll
            for (int j2 = 0; j2 < 4; j2++) {
                int off = offB[j2] + ks * 32;
                uint32_t r0, r1, r2, r3;
                ldsm4(r0, r1, r2, r3, sB + SW(off));
                bf[2 * j2][0] = r0; bf[2 * j2][1] = r1;
                bf[2 * j2 + 1][0] = r2; bf[2 * j2 + 1][1] = r3;
            }
#pragma unroll
            for (int mt = 0; mt < 2; mt++)
#pragma unroll
                for (int nt = 0; nt < 8; nt++)
                    mma16816(acc[mt][nt], af[mt], bf[nt][0], bf[nt][1]);
        }
        __syncthreads();
    }
#undef ISSUEG

    const int gid = lane >> 2, ctg = lane & 3;
#pragma unroll
    for (int mt = 0; mt < 2; mt++) {
        int m0 = tileM * 128 + wm + mt * 16 + gid;
#pragma unroll
        for (int nt = 0; nt < 8; nt++) {
            int n0 = tileN * 128 + wn + nt * 8 + ctg * 2;
            *(float2*)(C + (size_t)m0 * N + n0) =
                make_float2(acc[mt][nt][0], acc[mt][nt][1]);
            *(float2*)(C + (size_t)(m0 + 8) * N + n0) =
                make_float2(acc[mt][nt][2], acc[mt][nt][3]);
        }
    }
}

// ------------------------------------------------------------------
// fp32 -> fp16 conversion, 8 elems/thread.
// ------------------------------------------------------------------
__global__ __launch_bounds__(256)
void f2h_kernel(const float* __restrict__ in, __half* __restrict__ out)
{
    int idx = (blockIdx.x * 256 + threadIdx.x) * 8;
    float4 x0 = *(const float4*)(in + idx);
    float4 x1 = *(const float4*)(in + idx + 4);
    union { __half2 h[4]; uint4 u; } r;
    r.h[0] = __floats2half2_rn(x0.x, x0.y);
    r.h[1] = __floats2half2_rn(x0.z, x0.w);
    r.h[2] = __floats2half2_rn(x1.x, x1.y);
    r.h[3] = __floats2half2_rn(x1.z, x1.w);
    *(uint4*)(out + idx) = r.u;
}

// ------------------------------------------------------------------
// Fused conv(K=4)+SiLU+l2norm over one row segment.
// One block per row t. 512 threads, 8 channels each.
// q/k heads are 64 channels = 8 consecutive lanes -> shfl-group norm.
// ------------------------------------------------------------------
__global__ __launch_bounds__(512)
void conv_norm_seg(const float* __restrict__ mixed,
                   const float* __restrict__ w,
                   float* __restrict__ qkv, int row0)
{
    const int t  = row0 + blockIdx.x;
    const int c0 = threadIdx.x * 8;
    const size_t idx = (size_t)t * CDIM + c0;

    float x[8];
    {
        float4 a0 = *(const float4*)(mixed + idx);
        float4 a1 = *(const float4*)(mixed + idx + 4);
        float xs[8] = {a0.x, a0.y, a0.z, a0.w, a1.x, a1.y, a1.z, a1.w};
        float p1[8] = {0}, p2[8] = {0}, p3[8] = {0};
        if (t >= 1) {
            float4 b0 = *(const float4*)(mixed + idx - CDIM);
            float4 b1 = *(const float4*)(mixed + idx - CDIM + 4);
            p1[0]=b0.x;p1[1]=b0.y;p1[2]=b0.z;p1[3]=b0.w;p1[4]=b1.x;p1[5]=b1.y;p1[6]=b1.z;p1[7]=b1.w;
        }
        if (t >= 2) {
            float4 b0 = *(const float4*)(mixed + idx - 2 * CDIM);
            float4 b1 = *(const float4*)(mixed + idx - 2 * CDIM + 4);
            p2[0]=b0.x;p2[1]=b0.y;p2[2]=b0.z;p2[3]=b0.w;p2[4]=b1.x;p2[5]=b1.y;p2[6]=b1.z;p2[7]=b1.w;
        }
        if (t >= 3) {
            float4 b0 = *(const float4*)(mixed + idx - 3 * CDIM);
            float4 b1 = *(const float4*)(mixed + idx - 3 * CDIM + 4);
            p3[0]=b0.x;p3[1]=b0.y;p3[2]=b0.z;p3[3]=b0.w;p3[4]=b1.x;p3[5]=b1.y;p3[6]=b1.z;p3[7]=b1.w;
        }
#pragma unroll
        for (int j = 0; j < 8; j++) {
            float4 wj = *(const float4*)(w + (c0 + j) * 4);
            float acc = wj.w * xs[j];
            acc = fmaf(wj.z, p1[j], acc);
            acc = fmaf(wj.y, p2[j], acc);
            acc = fmaf(wj.x, p3[j], acc);
            x[j] = acc / (1.f + expf(-acc));   // silu
        }
    }

    if (c0 < 2 * KEYD) {
        float ss = 0.f;
#pragma unroll
        for (int j = 0; j < 8; j++) ss += x[j] * x[j];
        ss += __shfl_xor_sync(0xffffffffu, ss, 1);
        ss += __shfl_xor_sync(0xffffffffu, ss, 2);
        ss += __shfl_xor_sync(0xffffffffu, ss, 4);
        float r = rsqrtf(ss + 1e-6f);
        if (c0 < KEYD) r *= 0.125f;   // q scale 1/sqrt(64)
#pragma unroll
        for (int j = 0; j < 8; j++) x[j] *= r;
    }
    *(float4*)(qkv + idx)     = make_float4(x[0], x[1], x[2], x[3]);
    *(float4*)(qkv + idx + 4) = make_float4(x[4], x[5], x[6], x[7]);
}

// ------------------------------------------------------------------
// a/b projections -> (exp(g), beta) float2. One warp per (t,h).
// ------------------------------------------------------------------
__global__ __launch_bounds__(256)
void ab_kernel(const float* __restrict__ hs,
               const float* __restrict__ Wa,
               const float* __restrict__ Wb,
               const float* __restrict__ A_log,
               const float* __restrict__ dt_bias,
               float2* __restrict__ eb)
{
    int w    = blockIdx.x * (blockDim.x >> 5) + (threadIdx.x >> 5);
    int lane = threadIdx.x & 31;
    if (w >= SEQ * NH) return;
    int t = w >> 4, h = w & 15;

    const float4* x4 = (const float4*)(hs + (size_t)t * HID);
    const float4* a4 = (const float4*)(Wa + (size_t)h * HID);
    const float4* b4 = (const float4*)(Wb + (size_t)h * HID);

    float sa = 0.f, sb = 0.f;
    for (int i = lane; i < HID / 4; i += 32) {
        float4 x = x4[i], a = a4[i], b = b4[i];
        sa += x.x * a.x + x.y * a.y + x.z * a.z + x.w * a.w;
        sb += x.x * b.x + x.y * b.y + x.z * b.z + x.w * b.w;
    }
#pragma unroll
    for (int o = 16; o; o >>= 1) {
        sa += __shfl_xor_sync(0xffffffffu, sa, o);
        sb += __shfl_xor_sync(0xffffffffu, sb, o);
    }
    if (lane == 0) {
        float av = sa + dt_bias[h];
        float sp = (av > 20.f) ? av : log1pf(expf(av));
        eb[t * NH + h] = make_float2(expf(-expf(A_log[h]) * sp),
                                     1.f / (1.f + expf(-sb)));
    }
}

// ------------------------------------------------------------------
// Delta-rule scan SEGMENT [t0, tend). Warp-autonomous, register
// prefetch with 4 rotating buffers (distance-3 prefetch).
// 256 single-warp blocks: (head h = bid>>4, vgroup = bid&15).
// lane: qtr = lane&3 (16 of DK), vl = lane>>2 (8 v's per warp).
// ------------------------------------------------------------------
__global__ __launch_bounds__(32)
void scan_seg(const float* __restrict__ qkv,
              const float2* __restrict__ eb_arr,
              float* __restrict__ core,
              float* __restrict__ state,
              int t0, int tend)
{
    const int h    = blockIdx.x >> 4;
    const int vg   = blockIdx.x & 15;
    const int lane = threadIdx.x;
    const int qtr  = lane & 3;
    const int vl   = lane >> 2;
    const int v    = vg * 8 + vl;

    const float* kp = qkv + KEYD + h * DK + qtr * 16;
    const float* qp = qkv + h * DK + qtr * 16;
    const float* vp = qkv + 2 * KEYD + h * DV + v;
    float* sp = state + ((size_t)(h * DV + v)) * DK + qtr * 16;

    float4 kb[4][4], qb[4][4];
    float  vb[4], eg_[4], bt_[4];
    float  S[16];

    if (t0 == 0) {
#pragma unroll
        for (int i = 0; i < 16; i++) S[i] = 0.f;
    } else {
#pragma unroll
        for (int i = 0; i < 4; i++) {
            float4 s4 = ((const float4*)sp)[i];
            S[4 * i + 0] = s4.x; S[4 * i + 1] = s4.y;
            S[4 * i + 2] = s4.z; S[4 * i + 3] = s4.w;
        }
    }

#define LOADT(i, tt)                                                   \
    do {                                                               \
        int _t = (tt); if (_t >= SEQ) _t = SEQ - 1;                    \
        size_t _o = (size_t)_t * CDIM;                                 \
        const float4* _k4 = (const float4*)(kp + _o);                  \
        const float4* _q4 = (const float4*)(qp + _o);                  \
        kb[i][0] = _k4[0]; kb[i][1] = _k4[1];                          \
        kb[i][2] = _k4[2]; kb[i][3] = _k4[3];                          \
        qb[i][0] = _q4[0]; qb[i][1] = _q4[1];                          \
        qb[i][2] = _q4[2]; qb[i][3] = _q4[3];                          \
        vb[i] = vp[_o];                                                \
        float2 _e = eb_arr[_t * NH + h];                               \
        eg_[i] = _e.x; bt_[i] = _e.y;                                  \
    } while (0)

#define COMPUTE(i, t)                                                      \
    do {                                                                   \
        float r0 = 0.f, r1 = 0.f, r2 = 0.f, r3 = 0.f;                      \
        _Pragma("unroll")                                                  \
        for (int j = 0; j < 4; j++) {                                      \
            r0 = fmaf(kb[i][j].x, S[4 * j + 0], r0);                       \
            r1 = fmaf(kb[i][j].y, S[4 * j + 1], r1);                       \
            r2 = fmaf(kb[i][j].z, S[4 * j + 2], r2);                       \
            r3 = fmaf(kb[i][j].w, S[4 * j + 3], r3);                       \
        }                                                                  \
        float raw = (r0 + r1) + (r2 + r3);                                 \
        raw += __shfl_xor_sync(0xffffffffu, raw, 1);                       \
        raw += __shfl_xor_sync(0xffffffffu, raw, 2);                       \
        float _eg = eg_[i];                                                \
        float dl = (vb[i] - _eg * raw) * bt_[i];                           \
        float o0 = 0.f, o1 = 0.f, o2 = 0.f, o3 = 0.f;                      \
        _Pragma("unroll")                                                  \
        for (int j = 0; j < 4; j++) {                                      \
            float s0 = fmaf(S[4 * j + 0], _eg, kb[i][j].x * dl);           \
            float s1 = fmaf(S[4 * j + 1], _eg, kb[i][j].y * dl);           \
            float s2 = fmaf(S[4 * j + 2], _eg, kb[i][j].z * dl);           \
            float s3 = fmaf(S[4 * j + 3], _eg, kb[i][j].w * dl);           \
            S[4 * j + 0] = s0; S[4 * j + 1] = s1;                          \
            S[4 * j + 2] = s2; S[4 * j + 3] = s3;                          \
            o0 = fmaf(qb[i][j].x, s0, o0);                                 \
            o1 = fmaf(qb[i][j].y, s1, o1);                                 \
            o2 = fmaf(qb[i][j].z, s2, o2);                                 \
            o3 = fmaf(qb[i][j].w, s3, o3);                                 \
        }                                                                  \
        float o = (o0 + o1) + (o2 + o3);                                   \
        o += __shfl_xor_sync(0xffffffffu, o, 1);                           \
        o += __shfl_xor_sync(0xffffffffu, o, 2);                           \
        if (qtr == 0)                                                      \
            core[(size_t)(t) * VALD + h * DV + v] = o;                     \
    } while (0)

    LOADT(0, t0);
    LOADT(1, t0 + 1);
    LOADT(2, t0 + 2);

    // tend - t0 is a multiple of 4 (SEGR = 1024)
    for (int t = t0; t < tend; t += 4) {
        LOADT(3, t + 3);  COMPUTE(0, t);
        LOADT(0, t + 4);  COMPUTE(1, t + 1);
        LOADT(1, t + 5);  COMPUTE(2, t + 2);
        LOADT(2, t + 6);  COMPUTE(3, t + 3);
    }
#undef LOADT
#undef COMPUTE

#pragma unroll
    for (int i = 0; i < 4; i++)
        ((float4*)sp)[i] = make_float4(S[4 * i + 0], S[4 * i + 1],
                                       S[4 * i + 2], S[4 * i + 3]);
}

// ------------------------------------------------------------------
// Gated RMSNorm + SiLU(z), fp16 output, over one row segment.
// ------------------------------------------------------------------
__global__ __launch_bounds__(256)
void gate_norm_seg(const float* __restrict__ core,
                   const float* __restrict__ z,
                   const float* __restrict__ norm_w,
                   __half* __restrict__ out, int w0)
{
    int w    = w0 + blockIdx.x * (blockDim.x >> 5) + (threadIdx.x >> 5);
    int lane = threadIdx.x & 31;
    int t = w >> 4, h = w & 15;
    size_t base = (size_t)t * VALD + h * DV;

    float4 cv = ((const float4*)(core + base))[lane];
    float ss = cv.x * cv.x + cv.y * cv.y + cv.z * cv.z + cv.w * cv.w;
#pragma unroll
    for (int o = 16; o; o >>= 1) ss += __shfl_xor_sync(0xffffffffu, ss, o);
    float r = rsqrtf(ss * (1.f / DV) + 1e-6f);

    float4 zv = ((const float4*)(z + base))[lane];
    float4 nw = ((const float4*)norm_w)[lane];
    float v0 = cv.x * r * nw.x * (zv.x / (1.f + expf(-zv.x)));
    float v1 = cv.y * r * nw.y * (zv.y / (1.f + expf(-zv.y)));
    float v2 = cv.z * r * nw.z * (zv.z / (1.f + expf(-zv.z)));
    float v3 = cv.w * r * nw.w * (zv.w / (1.f + expf(-zv.w)));

    union { __half2 h[2]; uint2 u; } o2;
    o2.h[0] = __floats2half2_rn(v0, v1);
    o2.h[1] = __floats2half2_rn(v2, v3);
    *(uint2*)(out + base + lane * 4) = o2.u;
}

// ------------------------------------------------------------------
// Launch: 3-stream pipeline over 2 row segments (small graph).
// ------------------------------------------------------------------
static cudaStream_t g_sS = nullptr, g_sT = nullptr;
static cudaEvent_t  g_evFork, g_evHs, g_evAB, g_evEnd;
static cudaEvent_t  g_evQ[NSEG], g_evS[NSEG];

extern "C" void kernel_launch(void* const* d_in, const int* in_sizes, int n_in,
                              void* d_out, int out_size)
{
    const float* hs      = (const float*)d_in[0];
    const float* Wqkv    = (const float*)d_in[1];
    const float* Wa      = (const float*)d_in[2];
    const float* Wb      = (const float*)d_in[3];
    const float* Wz      = (const float*)d_in[4];
    const float* convw   = (const float*)d_in[5];
    const float* A_log   = (const float*)d_in[6];
    const float* dt_bias = (const float*)d_in[7];
    const float* norm_w  = (const float*)d_in[8];
    const float* Wout    = (const float*)d_in[9];
    float* out = (float*)d_out;

    if (!g_sS) {
        cudaStreamCreateWithFlags(&g_sS, cudaStreamNonBlocking);
        cudaStreamCreateWithFlags(&g_sT, cudaStreamNonBlocking);
        cudaEventCreateWithFlags(&g_evFork, cudaEventDisableTiming);
        cudaEventCreateWithFlags(&g_evHs,   cudaEventDisableTiming);
        cudaEventCreateWithFlags(&g_evAB,   cudaEventDisableTiming);
        cudaEventCreateWithFlags(&g_evEnd,  cudaEventDisableTiming);
        for (int b = 0; b < NSEG; b++) {
            cudaEventCreateWithFlags(&g_evQ[b], cudaEventDisableTiming);
            cudaEventCreateWithFlags(&g_evS[b], cudaEventDisableTiming);
        }
        cudaFuncSetAttribute(hgemm_nt,
                             cudaFuncAttributeMaxDynamicSharedMemorySize, HGEMM_SMEM);
    }

    float  *p_mixed, *p_qkv, *p_z, *p_core, *p_state;
    float2 *p_eb;
    __half *p_hs, *p_Wqkv, *p_Wz, *p_Wout, *p_gat;
    cudaGetSymbolAddress((void**)&p_mixed, g_mixed);
    cudaGetSymbolAddress((void**)&p_qkv,   g_qkv);
    cudaGetSymbolAddress((void**)&p_eb,    g_eb);
    cudaGetSymbolAddress((void**)&p_z,     g_z);
    cudaGetSymbolAddress((void**)&p_core,  g_core);
    cudaGetSymbolAddress((void**)&p_state, g_state);
    cudaGetSymbolAddress((void**)&p_hs,    g_hs_h);
    cudaGetSymbolAddress((void**)&p_Wqkv,  g_Wqkv_h);
    cudaGetSymbolAddress((void**)&p_Wz,    g_Wz_h);
    cudaGetSymbolAddress((void**)&p_Wout,  g_Wout_h);
    cudaGetSymbolAddress((void**)&p_gat,   g_gat_h);

    cudaEventRecord(g_evFork, 0);
    cudaStreamWaitEvent(g_sS, g_evFork, 0);
    cudaStreamWaitEvent(g_sT, g_evFork, 0);

    // ---- stream 0: conversions + segmented qkv GEMM + conv/norm ----
    f2h_kernel<<<(SEQ * HID / 8) / 256, 256>>>(hs, p_hs);
    cudaEventRecord(g_evHs, 0);
    f2h_kernel<<<(CDIM * HID / 8) / 256, 256>>>(Wqkv, p_Wqkv);

    for (int b = 0; b < NSEG; b++) {
        int row0 = b * SEGR;
        hgemm_nt<<<dim3(CDIM / 128, SEGR / 128), 256, HGEMM_SMEM>>>(
            p_hs + (size_t)row0 * HID, p_Wqkv,
            p_mixed + (size_t)row0 * CDIM, SEGR, CDIM, HID);
        conv_norm_seg<<<SEGR, 512>>>(p_mixed, convw, p_qkv, row0);
        cudaEventRecord(g_evQ[b], 0);
    }

    // ---- stream T: ab, z chain, Wout conversion ----
    ab_kernel<<<(SEQ * NH) / 8, 256, 0, g_sT>>>(hs, Wa, Wb, A_log, dt_bias, p_eb);
    cudaEventRecord(g_evAB, g_sT);
    f2h_kernel<<<(VALD * HID / 8) / 256, 256, 0, g_sT>>>(Wz, p_Wz);
    cudaStreamWaitEvent(g_sT, g_evHs, 0);
    hgemm_nt<<<dim3(VALD / 128, SEQ / 128), 256, HGEMM_SMEM, g_sT>>>(
        p_hs, p_Wz, p_z, SEQ, VALD, HID);
    f2h_kernel<<<(HID * VALD / 8) / 256, 256, 0, g_sT>>>(Wout, p_Wout);

    // ---- stream S: chained scan segments ----
    cudaStreamWaitEvent(g_sS, g_evAB, 0);
    for (int b = 0; b < NSEG; b++) {
        cudaStreamWaitEvent(g_sS, g_evQ[b], 0);
        scan_seg<<<256, 32, 0, g_sS>>>(p_qkv, p_eb, p_core, p_state,
                                       b * SEGR, (b + 1) * SEGR);
        cudaEventRecord(g_evS[b], g_sS);
    }

    // ---- stream T: gate + out GEMM per segment ----
    for (int b = 0; b < NSEG; b++) {
        int row0 = b * SEGR;
        cudaStreamWaitEvent(g_sT, g_evS[b], 0);
        gate_norm_seg<<<(SEGR * NH) / 8, 256, 0, g_sT>>>(
            p_core, p_z, norm_w, p_gat, row0 * NH);
        hgemm_nt<<<dim3(HID / 128, SEGR / 128), 256, HGEMM_SMEM, g_sT>>>(
            p_gat + (size_t)row0 * VALD, p_Wout,
            out + (size_t)row0 * HID, SEGR, HID, VALD);
    }
    cudaEventRecord(g_evEnd, g_sT);
    cudaStreamWaitEvent(0, g_evEnd, 0);
}

// round 10
// speedup vs baseline: 3.1925x; 1.1878x over previous
#include <cuda_runtime.h>
#include <cuda_fp16.h>
#include <math.h>
#include <stdint.h>

#define SEQ   2048
#define HID   2048
#define NH    16
#define DK    64
#define DV    128
#define KEYD  1024
#define VALD  2048
#define CDIM  4096   // 2*KEYD + VALD
#define NSEG  2
#define SEGR  (SEQ / NSEG)   // 1024 rows per segment
#define CHK   64
#define NCH   (SEQ / CHK)    // 32 chunks total
#define CHSEG (SEGR / CHK)   // 16 chunks per segment

// ------------------------------------------------------------------
// Scratch (device globals; no allocation allowed)
// ------------------------------------------------------------------
__device__ float  g_mixed[SEQ * CDIM];
__device__ float  g_qkv  [SEQ * CDIM];   // post conv+silu (q | k | v)
__device__ float2 g_eb   [SEQ * NH];     // (g, beta)  [raw log-decay]
__device__ float  g_z    [SEQ * VALD];
__device__ float  g_core [SEQ * VALD];
__device__ float  g_state[NH * 4 * 2048]; // per (h,dvs) 64x32 slices

// chunked WY factors
__device__ float  g_W  [NCH * NH * 64 * 64];
__device__ float  g_P  [NCH * NH * 64 * 64];
__device__ float  g_Qg [NCH * NH * 64 * 64];
__device__ float  g_KcT[NCH * NH * 64 * 64];
__device__ float  g_U0 [NCH * NH * 64 * 128];
__device__ float  g_gC [NCH * NH];

__device__ __half g_hs_h  [SEQ  * HID];
__device__ __half g_Wqkv_h[CDIM * HID];
__device__ __half g_Wz_h  [VALD * HID];
__device__ __half g_Wout_h[HID  * VALD];
__device__ __half g_gat_h [SEQ  * VALD];

// ------------------------------------------------------------------
// PTX helpers
// ------------------------------------------------------------------
__device__ __forceinline__ uint32_t smem_u32(const void* p) {
    uint32_t a;
    asm("{ .reg .u64 t; cvta.to.shared.u64 t, %1; cvt.u32.u64 %0, t; }"
        : "=r"(a) : "l"(p));
    return a;
}
__device__ __forceinline__ void cp_async16(uint32_t s, const void* g) {
    asm volatile("cp.async.cg.shared.global [%0], [%1], 16;" :: "r"(s), "l"(g));
}
__device__ __forceinline__ void cp_commit() {
    asm volatile("cp.async.commit_group;");
}
template <int N>
__device__ __forceinline__ void cp_wait() {
    asm volatile("cp.async.wait_group %0;" :: "n"(N));
}
__device__ __forceinline__ void ldsm4(uint32_t& r0, uint32_t& r1,
                                      uint32_t& r2, uint32_t& r3, uint32_t a) {
    asm volatile("ldmatrix.sync.aligned.m8n8.x4.shared.b16 {%0,%1,%2,%3}, [%4];"
                 : "=r"(r0), "=r"(r1), "=r"(r2), "=r"(r3) : "r"(a));
}
__device__ __forceinline__ void mma16816(float* d, const uint32_t* a,
                                         uint32_t b0, uint32_t b1) {
    asm volatile(
        "mma.sync.aligned.m16n8k16.row.col.f32.f16.f16.f32 "
        "{%0,%1,%2,%3}, {%4,%5,%6,%7}, {%8,%9}, {%0,%1,%2,%3};"
        : "+f"(d[0]), "+f"(d[1]), "+f"(d[2]), "+f"(d[3])
        : "r"(a[0]), "r"(a[1]), "r"(a[2]), "r"(a[3]), "r"(b0), "r"(b1));
}
#define SW(off) ((off) ^ (((off) >> 3) & 0x70))

// ------------------------------------------------------------------
// fp16 NT GEMM via mma.sync (unchanged, proven)
// ------------------------------------------------------------------
#define HGEMM_SMEM (4 * 16384)

__global__ __launch_bounds__(256)
void hgemm_nt(const __half* __restrict__ A, const __half* __restrict__ B,
              float* __restrict__ C, int M, int N, int K)
{
    extern __shared__ __align__(1024) char sm[];
    const int tid  = threadIdx.x;
    const int wid  = tid >> 5, lane = tid & 31;
    const int tileN = blockIdx.x, tileM = blockIdx.y;
    const int wm = (wid >> 1) * 32;
    const int wn = (wid & 1) * 64;

    const uint32_t sbase = smem_u32(sm);
    const char* Ag = (const char*)(A + (size_t)tileM * 128 * K);
    const char* Bg = (const char*)(B + (size_t)tileN * 128 * K);
    const size_t rs = (size_t)K * 2;
    const int crow = tid >> 3;
    const int ccol = (tid & 7) * 16;

    int offA[2], offB[4];
#pragma unroll
    for (int mt = 0; mt < 2; mt++)
        offA[mt] = (wm + mt * 16 + (lane & 15)) * 128 + (lane >> 4) * 16;
#pragma unroll
    for (int j2 = 0; j2 < 4; j2++)
        offB[j2] = (wn + j2 * 16 + (lane & 7) + ((lane >> 4) & 1) * 8) * 128
                 + ((lane >> 3) & 1) * 16;

    float acc[2][8][4];
#pragma unroll
    for (int mt = 0; mt < 2; mt++)
#pragma unroll
        for (int nt = 0; nt < 8; nt++)
#pragma unroll
            for (int r = 0; r < 4; r++) acc[mt][nt][r] = 0.f;

    const int chunks = K >> 6;

#define ISSUEG(i, b)                                                         \
    do {                                                                     \
        uint32_t sA = sbase + (b) * 32768;                                   \
        uint32_t sB = sA + 16384;                                            \
        const char* gA = Ag + (size_t)(i) * 128 + ccol;                      \
        const char* gB = Bg + (size_t)(i) * 128 + ccol;                      \
        _Pragma("unroll")                                                    \
        for (int p = 0; p < 4; p++) {                                        \
            int row = crow + p * 32;                                         \
            int so  = SW(row * 128 + ccol);                                  \
            cp_async16(sA + so, gA + row * rs);                              \
            cp_async16(sB + so, gB + row * rs);                              \
        }                                                                    \
        cp_commit();                                                         \
    } while (0)

    ISSUEG(0, 0);
    for (int i = 0; i < chunks; i++) {
        const int b = i & 1;
        if (i + 1 < chunks) { ISSUEG(i + 1, b ^ 1); cp_wait<1>(); }
        else                { cp_wait<0>(); }
        __syncthreads();
        const uint32_t sA = sbase + b * 32768;
        const uint32_t sB = sA + 16384;
#pragma unroll
        for (int ks = 0; ks < 4; ks++) {
            uint32_t af[2][4];
#pragma unroll
            for (int mt = 0; mt < 2; mt++) {
                int off = offA[mt] + ks * 32;
                ldsm4(af[mt][0], af[mt][1], af[mt][2], af[mt][3], sA + SW(off));
            }
            uint32_t bf[8][2];
#pragma unroll
            for (int j2 = 0; j2 < 4; j2++) {
                int off = offB[j2] + ks * 32;
                uint32_t r0, r1, r2, r3;
                ldsm4(r0, r1, r2, r3, sB + SW(off));
                bf[2 * j2][0] = r0; bf[2 * j2][1] = r1;
                bf[2 * j2 + 1][0] = r2; bf[2 * j2 + 1][1] = r3;
            }
#pragma unroll
            for (int mt = 0; mt < 2; mt++)
#pragma unroll
                for (int nt = 0; nt < 8; nt++)
                    mma16816(acc[mt][nt], af[mt], bf[nt][0], bf[nt][1]);
        }
        __syncthreads();
    }
#undef ISSUEG

    const int gid = lane >> 2, ctg = lane & 3;
#pragma unroll
    for (int mt = 0; mt < 2; mt++) {
        int m0 = tileM * 128 + wm + mt * 16 + gid;
#pragma unroll
        for (int nt = 0; nt < 8; nt++) {
            int n0 = tileN * 128 + wn + nt * 8 + ctg * 2;
            *(float2*)(C + (size_t)m0 * N + n0) =
                make_float2(acc[mt][nt][0], acc[mt][nt][1]);
            *(float2*)(C + (size_t)(m0 + 8) * N + n0) =
                make_float2(acc[mt][nt][2], acc[mt][nt][3]);
        }
    }
}

// ------------------------------------------------------------------
// fp32 -> fp16, 8 elems/thread.
// ------------------------------------------------------------------
__global__ __launch_bounds__(256)
void f2h_kernel(const float* __restrict__ in, __half* __restrict__ out)
{
    int idx = (blockIdx.x * 256 + threadIdx.x) * 8;
    float4 x0 = *(const float4*)(in + idx);
    float4 x1 = *(const float4*)(in + idx + 4);
    union { __half2 h[4]; uint4 u; } r;
    r.h[0] = __floats2half2_rn(x0.x, x0.y);
    r.h[1] = __floats2half2_rn(x0.z, x0.w);
    r.h[2] = __floats2half2_rn(x1.x, x1.y);
    r.h[3] = __floats2half2_rn(x1.z, x1.w);
    *(uint4*)(out + idx) = r.u;
}

// ------------------------------------------------------------------
// Fused conv(K=4)+SiLU+l2norm over one row segment (unchanged).
// ------------------------------------------------------------------
__global__ __launch_bounds__(512)
void conv_norm_seg(const float* __restrict__ mixed,
                   const float* __restrict__ w,
                   float* __restrict__ qkv, int row0)
{
    const int t  = row0 + blockIdx.x;
    const int c0 = threadIdx.x * 8;
    const size_t idx = (size_t)t * CDIM + c0;

    float x[8];
    {
        float4 a0 = *(const float4*)(mixed + idx);
        float4 a1 = *(const float4*)(mixed + idx + 4);
        float xs[8] = {a0.x, a0.y, a0.z, a0.w, a1.x, a1.y, a1.z, a1.w};
        float p1[8] = {0}, p2[8] = {0}, p3[8] = {0};
        if (t >= 1) {
            float4 b0 = *(const float4*)(mixed + idx - CDIM);
            float4 b1 = *(const float4*)(mixed + idx - CDIM + 4);
            p1[0]=b0.x;p1[1]=b0.y;p1[2]=b0.z;p1[3]=b0.w;p1[4]=b1.x;p1[5]=b1.y;p1[6]=b1.z;p1[7]=b1.w;
        }
        if (t >= 2) {
            float4 b0 = *(const float4*)(mixed + idx - 2 * CDIM);
            float4 b1 = *(const float4*)(mixed + idx - 2 * CDIM + 4);
            p2[0]=b0.x;p2[1]=b0.y;p2[2]=b0.z;p2[3]=b0.w;p2[4]=b1.x;p2[5]=b1.y;p2[6]=b1.z;p2[7]=b1.w;
        }
        if (t >= 3) {
            float4 b0 = *(const float4*)(mixed + idx - 3 * CDIM);
            float4 b1 = *(const float4*)(mixed + idx - 3 * CDIM + 4);
            p3[0]=b0.x;p3[1]=b0.y;p3[2]=b0.z;p3[3]=b0.w;p3[4]=b1.x;p3[5]=b1.y;p3[6]=b1.z;p3[7]=b1.w;
        }
#pragma unroll
        for (int j = 0; j < 8; j++) {
            float4 wj = *(const float4*)(w + (c0 + j) * 4);
            float acc = wj.w * xs[j];
            acc = fmaf(wj.z, p1[j], acc);
            acc = fmaf(wj.y, p2[j], acc);
            acc = fmaf(wj.x, p3[j], acc);
            x[j] = acc / (1.f + expf(-acc));
        }
    }
    if (c0 < 2 * KEYD) {
        float ss = 0.f;
#pragma unroll
        for (int j = 0; j < 8; j++) ss += x[j] * x[j];
        ss += __shfl_xor_sync(0xffffffffu, ss, 1);
        ss += __shfl_xor_sync(0xffffffffu, ss, 2);
        ss += __shfl_xor_sync(0xffffffffu, ss, 4);
        float r = rsqrtf(ss + 1e-6f);
        if (c0 < KEYD) r *= 0.125f;
#pragma unroll
        for (int j = 0; j < 8; j++) x[j] *= r;
    }
    *(float4*)(qkv + idx)     = make_float4(x[0], x[1], x[2], x[3]);
    *(float4*)(qkv + idx + 4) = make_float4(x[4], x[5], x[6], x[7]);
}

// ------------------------------------------------------------------
// a/b projections -> (g, beta).   g = raw log-decay.
// ------------------------------------------------------------------
__global__ __launch_bounds__(256)
void ab_kernel(const float* __restrict__ hs,
               const float* __restrict__ Wa,
               const float* __restrict__ Wb,
               const float* __restrict__ A_log,
               const float* __restrict__ dt_bias,
               float2* __restrict__ eb)
{
    int w    = blockIdx.x * (blockDim.x >> 5) + (threadIdx.x >> 5);
    int lane = threadIdx.x & 31;
    if (w >= SEQ * NH) return;
    int t = w >> 4, h = w & 15;

    const float4* x4 = (const float4*)(hs + (size_t)t * HID);
    const float4* a4 = (const float4*)(Wa + (size_t)h * HID);
    const float4* b4 = (const float4*)(Wb + (size_t)h * HID);

    float sa = 0.f, sb = 0.f;
    for (int i = lane; i < HID / 4; i += 32) {
        float4 x = x4[i], a = a4[i], b = b4[i];
        sa += x.x * a.x + x.y * a.y + x.z * a.z + x.w * a.w;
        sb += x.x * b.x + x.y * b.y + x.z * b.z + x.w * b.w;
    }
#pragma unroll
    for (int o = 16; o; o >>= 1) {
        sa += __shfl_xor_sync(0xffffffffu, sa, o);
        sb += __shfl_xor_sync(0xffffffffu, sb, o);
    }
    if (lane == 0) {
        float av = sa + dt_bias[h];
        float sp = (av > 20.f) ? av : log1pf(expf(av));
        eb[t * NH + h] = make_float2(-expf(A_log[h]) * sp,
                                     1.f / (1.f + expf(-sb)));
    }
}

// ------------------------------------------------------------------
// Phase 1: per-chunk WY factors. Grid (CHSEG, NH), 256 threads.
// Computes W, P, Qg, KcT, U0, gC for chunk c = c0 + bx, head h = by.
// All decay ratios via log-space cumsum (no underflow NaNs).
// ------------------------------------------------------------------
#define PREP_SMEM ((4 * 64 * 68 + 64 * 132 + 3 * 64) * 4)

__global__ __launch_bounds__(256)
void chunk_prep(const float* __restrict__ qkv,
                const float2* __restrict__ eb,
                float* __restrict__ Wg,  float* __restrict__ Pg,
                float* __restrict__ Qgg, float* __restrict__ KcTg,
                float* __restrict__ U0g, float* __restrict__ gCg,
                int c0)
{
    const int c = c0 + blockIdx.x;
    const int h = blockIdx.y;
    const int tid = threadIdx.x;
    const int t0 = c * CHK;

    extern __shared__ float smp[];
    float* Ks  = smp;                // [64][68]
    float* Qs  = Ks  + 64 * 68;
    float* Ms  = Qs  + 64 * 68;
    float* Ts  = Ms  + 64 * 68;
    float* Vs  = Ts  + 64 * 68;     // [64][132]
    float* lg  = Vs  + 64 * 132;    // [64]
    float* bet = lg  + 64;
    float* sK  = bet + 64;

    // load K, Q (64 rows x 16 float4)
    for (int i = tid; i < 64 * 16; i += 256) {
        int r = i >> 4, j4 = i & 15;
        const float* row = qkv + (size_t)(t0 + r) * CDIM;
        *(float4*)&Qs[r * 68 + j4 * 4] = *(const float4*)(row + h * 64 + j4 * 4);
        *(float4*)&Ks[r * 68 + j4 * 4] = *(const float4*)(row + KEYD + h * 64 + j4 * 4);
    }
    // V (64 rows x 32 float4)
    for (int i = tid; i < 64 * 32; i += 256) {
        int r = i >> 5, j4 = i & 31;
        const float* row = qkv + (size_t)(t0 + r) * CDIM;
        *(float4*)&Vs[r * 132 + j4 * 4] = *(const float4*)(row + 2 * KEYD + h * DV + j4 * 4);
    }
    if (tid < 64) {
        float2 e = eb[(t0 + tid) * NH + h];
        lg[tid]  = e.x;    // raw g; cumsum next
        bet[tid] = e.y;
    }
    __syncthreads();
    if (tid == 0) {
        float a = 0.f;
        for (int t = 0; t < 64; t++) { a += lg[t]; lg[t] = a; }
    }
    __syncthreads();

    // G = K K^T -> M ;  QK = Q K^T -> P (decayed, masked)
    {
        const int t  = tid >> 2;
        const int sb = (tid & 3) * 16;
        float ak[16], aq[16];
#pragma unroll
        for (int i = 0; i < 16; i++) { ak[i] = 0.f; aq[i] = 0.f; }
        for (int jb = 0; jb < 16; jb++) {
            float4 kt = *(const float4*)&Ks[t * 68 + jb * 4];
            float4 qt = *(const float4*)&Qs[t * 68 + jb * 4];
#pragma unroll
            for (int si = 0; si < 16; si++) {
                float4 ks = *(const float4*)&Ks[(sb + si) * 68 + jb * 4];
                ak[si] += kt.x * ks.x + kt.y * ks.y + kt.z * ks.z + kt.w * ks.w;
                aq[si] += qt.x * ks.x + qt.y * ks.y + qt.z * ks.z + qt.w * ks.w;
            }
        }
        float lgt = lg[t], bt = bet[t];
        float* Pout = Pg + ((size_t)(c * NH + h) << 12);
#pragma unroll
        for (int si = 0; si < 16; si++) {
            int s = sb + si;
            float rr = expf(lgt - lg[s]);
            Ms[t * 68 + s]  = (s < t)  ? bt * rr * ak[si] : 0.f;
            Pout[t * 64 + s] = (s <= t) ? rr * aq[si] : 0.f;
        }
    }
    __syncthreads();

    // T = (I+M)^{-1} (threads 0..63, column-independent); others: Qg, KcT
    if (tid < 64) {
        const int cc = tid;
        for (int i = 0; i < 64; i++) {
            float acc = (i == cc) ? 1.f : 0.f;
            for (int j = 0; j < i; j++)
                acc -= Ms[i * 68 + j] * Ts[j * 68 + cc];
            Ts[i * 68 + cc] = acc;
        }
        sK[cc] = bet[cc] * expf(lg[cc]);
    } else {
        float lgC = lg[63];
        float* Qout = Qgg  + ((size_t)(c * NH + h) << 12);
        float* Kout = KcTg + ((size_t)(c * NH + h) << 12);
        for (int i = tid - 64; i < 4096; i += 192) {
            int t = i >> 6, d_ = i & 63;
            Qout[i] = expf(lg[t]) * Qs[t * 68 + d_];
            // KcT[j=t][s=d_] = exp(lgC - lg[s]) * K[s][j]
            Kout[i] = expf(lgC - lg[d_]) * Ks[d_ * 68 + t];
        }
        if (tid == 64) gCg[c * NH + h] = expf(lgC);
    }
    __syncthreads();

    // W = T diag(beta*Gamma) K
    {
        const int t  = tid >> 2;
        const int db = (tid & 3) * 16;
        float acc[16];
#pragma unroll
        for (int i = 0; i < 16; i++) acc[i] = 0.f;
        for (int j = 0; j < 64; j++) {
            float m = Ts[t * 68 + j] * sK[j];
#pragma unroll
            for (int i4 = 0; i4 < 4; i4++) {
                float4 kv = *(const float4*)&Ks[j * 68 + db + i4 * 4];
                acc[i4 * 4 + 0] = fmaf(m, kv.x, acc[i4 * 4 + 0]);
                acc[i4 * 4 + 1] = fmaf(m, kv.y, acc[i4 * 4 + 1]);
                acc[i4 * 4 + 2] = fmaf(m, kv.z, acc[i4 * 4 + 2]);
                acc[i4 * 4 + 3] = fmaf(m, kv.w, acc[i4 * 4 + 3]);
            }
        }
        float* Wout = Wg + ((size_t)(c * NH + h) << 12);
#pragma unroll
        for (int i4 = 0; i4 < 4; i4++)
            *(float4*)&Wout[t * 64 + db + i4 * 4] =
                make_float4(acc[i4*4], acc[i4*4+1], acc[i4*4+2], acc[i4*4+3]);
    }
    // U0 = T diag(beta) V
    {
        const int t  = tid >> 2;
        const int db = (tid & 3) * 32;
        float acc[32];
#pragma unroll
        for (int i = 0; i < 32; i++) acc[i] = 0.f;
        for (int j = 0; j < 64; j++) {
            float m = Ts[t * 68 + j] * bet[j];
#pragma unroll
            for (int i4 = 0; i4 < 8; i4++) {
                float4 vv = *(const float4*)&Vs[j * 132 + db + i4 * 4];
                acc[i4 * 4 + 0] = fmaf(m, vv.x, acc[i4 * 4 + 0]);
                acc[i4 * 4 + 1] = fmaf(m, vv.y, acc[i4 * 4 + 1]);
                acc[i4 * 4 + 2] = fmaf(m, vv.z, acc[i4 * 4 + 2]);
                acc[i4 * 4 + 3] = fmaf(m, vv.w, acc[i4 * 4 + 3]);
            }
        }
        float* Uout = U0g + ((size_t)(c * NH + h) << 13);
#pragma unroll
        for (int i4 = 0; i4 < 8; i4++)
            *(float4*)&Uout[t * 128 + db + i4 * 4] =
                make_float4(acc[i4*4], acc[i4*4+1], acc[i4*4+2], acc[i4*4+3]);
    }
}

// ------------------------------------------------------------------
// Phase 2: sequential chunk recurrence. Grid (4, NH), 256 threads.
// CTA owns (head h, DV slice of 32). Per chunk:
//   u = U0 - W S ; O = Qg S + P u ; S = gC S + KcT u.
// ------------------------------------------------------------------
#define SCAN_SMEM ((4 * 64 * 68 + 2 * 64 * 33) * 4)

__global__ __launch_bounds__(256)
void chunk_scan(const float* __restrict__ Wg,  const float* __restrict__ Pg,
                const float* __restrict__ Qgg, const float* __restrict__ KcTg,
                const float* __restrict__ U0g, const float* __restrict__ gCg,
                float* __restrict__ core, float* __restrict__ state,
                int c0, int nch)
{
    const int dvs = blockIdx.x;
    const int h   = blockIdx.y;
    const int tid = threadIdx.x;
    const int d   = tid & 31;
    const int tt  = tid >> 5;

    extern __shared__ float sms[];
    float* Ws  = sms;               // [64][68]
    float* Ps  = Ws  + 64 * 68;
    float* Qgs = Ps  + 64 * 68;
    float* Kts = Qgs + 64 * 68;
    float* Ss  = Kts + 64 * 68;     // [64][33]
    float* us  = Ss  + 64 * 33;

    float* stbase = state + (size_t)(h * 4 + dvs) * 2048;

    if (c0 == 0) {
#pragma unroll
        for (int r = 0; r < 8; r++) Ss[(tt * 8 + r) * 33 + d] = 0.f;
    } else {
#pragma unroll
        for (int r = 0; r < 8; r++)
            Ss[(tt * 8 + r) * 33 + d] = stbase[(tt * 8 + r) * 32 + d];
    }
    __syncthreads();

    for (int cc = 0; cc < nch; cc++) {
        const int cidx = c0 + cc;
        const size_t b4k = (size_t)(cidx * NH + h) << 12;
        for (int i = tid; i < 1024; i += 256) {
            int r = i >> 4, c4 = (i & 15) * 4;
            *(float4*)&Ws [r * 68 + c4] = *(const float4*)(Wg   + b4k + i * 4);
            *(float4*)&Ps [r * 68 + c4] = *(const float4*)(Pg   + b4k + i * 4);
            *(float4*)&Qgs[r * 68 + c4] = *(const float4*)(Qgg  + b4k + i * 4);
            *(float4*)&Kts[r * 68 + c4] = *(const float4*)(KcTg + b4k + i * 4);
        }
        float gC = gCg[cidx * NH + h];
        __syncthreads();

        // u = U0 - W S
        const float* U0p = U0g + ((size_t)(cidx * NH + h) << 13) + dvs * 32 + d;
        float uacc[8];
#pragma unroll
        for (int r = 0; r < 8; r++) uacc[r] = U0p[(tt * 8 + r) * 128];
        for (int jb = 0; jb < 16; jb++) {
            float s0 = Ss[(jb * 4 + 0) * 33 + d];
            float s1 = Ss[(jb * 4 + 1) * 33 + d];
            float s2 = Ss[(jb * 4 + 2) * 33 + d];
            float s3 = Ss[(jb * 4 + 3) * 33 + d];
#pragma unroll
            for (int r = 0; r < 8; r++) {
                float4 wv = *(const float4*)&Ws[(tt * 8 + r) * 68 + jb * 4];
                uacc[r] -= wv.x * s0 + wv.y * s1 + wv.z * s2 + wv.w * s3;
            }
        }
#pragma unroll
        for (int r = 0; r < 8; r++) us[(tt * 8 + r) * 33 + d] = uacc[r];
        __syncthreads();

        // O = Qg S + P u
        float oacc[8];
#pragma unroll
        for (int r = 0; r < 8; r++) oacc[r] = 0.f;
        for (int jb = 0; jb < 16; jb++) {
            float s0 = Ss[(jb*4+0)*33 + d], s1 = Ss[(jb*4+1)*33 + d];
            float s2 = Ss[(jb*4+2)*33 + d], s3 = Ss[(jb*4+3)*33 + d];
            float u0 = us[(jb*4+0)*33 + d], u1 = us[(jb*4+1)*33 + d];
            float u2 = us[(jb*4+2)*33 + d], u3 = us[(jb*4+3)*33 + d];
#pragma unroll
            for (int r = 0; r < 8; r++) {
                float4 qv = *(const float4*)&Qgs[(tt * 8 + r) * 68 + jb * 4];
                float4 pv = *(const float4*)&Ps [(tt * 8 + r) * 68 + jb * 4];
                oacc[r] += qv.x * s0 + qv.y * s1 + qv.z * s2 + qv.w * s3
                         + pv.x * u0 + pv.y * u1 + pv.z * u2 + pv.w * u3;
            }
        }
        // S' = gC S + KcT u   (row j = tt*8+r)
        float sacc[8];
#pragma unroll
        for (int r = 0; r < 8; r++) sacc[r] = gC * Ss[(tt * 8 + r) * 33 + d];
        for (int sb = 0; sb < 16; sb++) {
            float u0 = us[(sb*4+0)*33 + d], u1 = us[(sb*4+1)*33 + d];
            float u2 = us[(sb*4+2)*33 + d], u3 = us[(sb*4+3)*33 + d];
#pragma unroll
            for (int r = 0; r < 8; r++) {
                float4 kv = *(const float4*)&Kts[(tt * 8 + r) * 68 + sb * 4];
                sacc[r] += kv.x * u0 + kv.y * u1 + kv.z * u2 + kv.w * u3;
            }
        }
        __syncthreads();

        float* corep = core + (size_t)(cidx * CHK) * VALD + h * DV + dvs * 32 + d;
#pragma unroll
        for (int r = 0; r < 8; r++)
            corep[(size_t)(tt * 8 + r) * VALD] = oacc[r];
#pragma unroll
        for (int r = 0; r < 8; r++) Ss[(tt * 8 + r) * 33 + d] = sacc[r];
        __syncthreads();
    }
#pragma unroll
    for (int r = 0; r < 8; r++)
        stbase[(tt * 8 + r) * 32 + d] = Ss[(tt * 8 + r) * 33 + d];
}

// ------------------------------------------------------------------
// Gated RMSNorm + SiLU(z), fp16 output, per row segment.
// ------------------------------------------------------------------
__global__ __launch_bounds__(256)
void gate_norm_seg(const float* __restrict__ core,
                   const float* __restrict__ z,
                   const float* __restrict__ norm_w,
                   __half* __restrict__ out, int w0)
{
    int w    = w0 + blockIdx.x * (blockDim.x >> 5) + (threadIdx.x >> 5);
    int lane = threadIdx.x & 31;
    int t = w >> 4, h = w & 15;
    size_t base = (size_t)t * VALD + h * DV;

    float4 cv = ((const float4*)(core + base))[lane];
    float ss = cv.x * cv.x + cv.y * cv.y + cv.z * cv.z + cv.w * cv.w;
#pragma unroll
    for (int o = 16; o; o >>= 1) ss += __shfl_xor_sync(0xffffffffu, ss, o);
    float r = rsqrtf(ss * (1.f / DV) + 1e-6f);

    float4 zv = ((const float4*)(z + base))[lane];
    float4 nw = ((const float4*)norm_w)[lane];
    float v0 = cv.x * r * nw.x * (zv.x / (1.f + expf(-zv.x)));
    float v1 = cv.y * r * nw.y * (zv.y / (1.f + expf(-zv.y)));
    float v2 = cv.z * r * nw.z * (zv.z / (1.f + expf(-zv.z)));
    float v3 = cv.w * r * nw.w * (zv.w / (1.f + expf(-zv.w)));

    union { __half2 h2[2]; uint2 u; } o2;
    o2.h2[0] = __floats2half2_rn(v0, v1);
    o2.h2[1] = __floats2half2_rn(v2, v3);
    *(uint2*)(out + base + lane * 4) = o2.u;
}

// ------------------------------------------------------------------
// Launch: 4-stream pipeline over 2 segments.
// ------------------------------------------------------------------
static cudaStream_t g_sP = nullptr, g_sS = nullptr, g_sT = nullptr;
static cudaEvent_t  g_evFork, g_evHs, g_evAB, g_evEnd;
static cudaEvent_t  g_evQ[NSEG], g_evP[NSEG], g_evS[NSEG];

extern "C" void kernel_launch(void* const* d_in, const int* in_sizes, int n_in,
                              void* d_out, int out_size)
{
    const float* hs      = (const float*)d_in[0];
    const float* Wqkv    = (const float*)d_in[1];
    const float* Wa      = (const float*)d_in[2];
    const float* Wb      = (const float*)d_in[3];
    const float* Wz      = (const float*)d_in[4];
    const float* convw   = (const float*)d_in[5];
    const float* A_log   = (const float*)d_in[6];
    const float* dt_bias = (const float*)d_in[7];
    const float* norm_w  = (const float*)d_in[8];
    const float* Wout    = (const float*)d_in[9];
    float* out = (float*)d_out;

    if (!g_sS) {
        cudaStreamCreateWithFlags(&g_sP, cudaStreamNonBlocking);
        cudaStreamCreateWithFlags(&g_sS, cudaStreamNonBlocking);
        cudaStreamCreateWithFlags(&g_sT, cudaStreamNonBlocking);
        cudaEventCreateWithFlags(&g_evFork, cudaEventDisableTiming);
        cudaEventCreateWithFlags(&g_evHs,   cudaEventDisableTiming);
        cudaEventCreateWithFlags(&g_evAB,   cudaEventDisableTiming);
        cudaEventCreateWithFlags(&g_evEnd,  cudaEventDisableTiming);
        for (int b = 0; b < NSEG; b++) {
            cudaEventCreateWithFlags(&g_evQ[b], cudaEventDisableTiming);
            cudaEventCreateWithFlags(&g_evP[b], cudaEventDisableTiming);
            cudaEventCreateWithFlags(&g_evS[b], cudaEventDisableTiming);
        }
        cudaFuncSetAttribute(hgemm_nt,
                             cudaFuncAttributeMaxDynamicSharedMemorySize, HGEMM_SMEM);
        cudaFuncSetAttribute(chunk_prep,
                             cudaFuncAttributeMaxDynamicSharedMemorySize, PREP_SMEM);
        cudaFuncSetAttribute(chunk_scan,
                             cudaFuncAttributeMaxDynamicSharedMemorySize, SCAN_SMEM);
    }

    float  *p_mixed, *p_qkv, *p_z, *p_core, *p_state;
    float  *p_W, *p_P, *p_Qg, *p_KcT, *p_U0, *p_gC;
    float2 *p_eb;
    __half *p_hs, *p_Wqkv, *p_Wz, *p_Wout, *p_gat;
    cudaGetSymbolAddress((void**)&p_mixed, g_mixed);
    cudaGetSymbolAddress((void**)&p_qkv,   g_qkv);
    cudaGetSymbolAddress((void**)&p_eb,    g_eb);
    cudaGetSymbolAddress((void**)&p_z,     g_z);
    cudaGetSymbolAddress((void**)&p_core,  g_core);
    cudaGetSymbolAddress((void**)&p_state, g_state);
    cudaGetSymbolAddress((void**)&p_W,     g_W);
    cudaGetSymbolAddress((void**)&p_P,     g_P);
    cudaGetSymbolAddress((void**)&p_Qg,    g_Qg);
    cudaGetSymbolAddress((void**)&p_KcT,   g_KcT);
    cudaGetSymbolAddress((void**)&p_U0,    g_U0);
    cudaGetSymbolAddress((void**)&p_gC,    g_gC);
    cudaGetSymbolAddress((void**)&p_hs,    g_hs_h);
    cudaGetSymbolAddress((void**)&p_Wqkv,  g_Wqkv_h);
    cudaGetSymbolAddress((void**)&p_Wz,    g_Wz_h);
    cudaGetSymbolAddress((void**)&p_Wout,  g_Wout_h);
    cudaGetSymbolAddress((void**)&p_gat,   g_gat_h);

    cudaEventRecord(g_evFork, 0);
    cudaStreamWaitEvent(g_sP, g_evFork, 0);
    cudaStreamWaitEvent(g_sS, g_evFork, 0);
    cudaStreamWaitEvent(g_sT, g_evFork, 0);

    // stream 0: conversions + segmented qkv GEMM + conv/norm
    f2h_kernel<<<(SEQ * HID / 8) / 256, 256>>>(hs, p_hs);
    cudaEventRecord(g_evHs, 0);
    f2h_kernel<<<(CDIM * HID / 8) / 256, 256>>>(Wqkv, p_Wqkv);
    for (int b = 0; b < NSEG; b++) {
        int row0 = b * SEGR;
        hgemm_nt<<<dim3(CDIM / 128, SEGR / 128), 256, HGEMM_SMEM>>>(
            p_hs + (size_t)row0 * HID, p_Wqkv,
            p_mixed + (size_t)row0 * CDIM, SEGR, CDIM, HID);
        conv_norm_seg<<<SEGR, 512>>>(p_mixed, convw, p_qkv, row0);
        cudaEventRecord(g_evQ[b], 0);
    }

    // stream T: ab, z chain, Wout conversion
    ab_kernel<<<(SEQ * NH) / 8, 256, 0, g_sT>>>(hs, Wa, Wb, A_log, dt_bias, p_eb);
    cudaEventRecord(g_evAB, g_sT);
    f2h_kernel<<<(VALD * HID / 8) / 256, 256, 0, g_sT>>>(Wz, p_Wz);
    cudaStreamWaitEvent(g_sT, g_evHs, 0);
    hgemm_nt<<<dim3(VALD / 128, SEQ / 128), 256, HGEMM_SMEM, g_sT>>>(
        p_hs, p_Wz, p_z, SEQ, VALD, HID);
    f2h_kernel<<<(HID * VALD / 8) / 256, 256, 0, g_sT>>>(Wout, p_Wout);

    // stream P: chunk prep per segment
    cudaStreamWaitEvent(g_sP, g_evAB, 0);
    for (int b = 0; b < NSEG; b++) {
        cudaStreamWaitEvent(g_sP, g_evQ[b], 0);
        chunk_prep<<<dim3(CHSEG, NH), 256, PREP_SMEM, g_sP>>>(
            p_qkv, p_eb, p_W, p_P, p_Qg, p_KcT, p_U0, p_gC, b * CHSEG);
        cudaEventRecord(g_evP[b], g_sP);
    }

    // stream S: sequential chunk recurrence per segment
    for (int b = 0; b < NSEG; b++) {
        cudaStreamWaitEvent(g_sS, g_evP[b], 0);
        chunk_scan<<<dim3(4, NH), 256, SCAN_SMEM, g_sS>>>(
            p_W, p_P, p_Qg, p_KcT, p_U0, p_gC, p_core, p_state,
            b * CHSEG, CHSEG);
        cudaEventRecord(g_evS[b], g_sS);
    }

    // stream T: gate + out GEMM per segment
    for (int b = 0; b < NSEG; b++) {
        int row0 = b * SEGR;
        cudaStreamWaitEvent(g_sT, g_evS[b], 0);
        gate_norm_seg<<<(SEGR * NH) / 8, 256, 0, g_sT>>>(
            p_core, p_z, norm_w, p_gat, row0 * NH);
        hgemm_nt<<<dim3(HID / 128, SEGR / 128), 256, HGEMM_SMEM, g_sT>>>(
            p_gat + (size_t)row0 * VALD, p_Wout,
            out + (size_t)row0 * HID, SEGR, HID, VALD);
    }
    cudaEventRecord(g_evEnd, g_sT);
    cudaStreamWaitEvent(0, g_evEnd, 0);
}

// round 11
// speedup vs baseline: 3.5305x; 1.1059x over previous
#include <cuda_runtime.h>
#include <cuda_fp16.h>
#include <math.h>
#include <stdint.h>

#define SEQ   2048
#define HID   2048
#define NH    16
#define DK    64
#define DV    128
#define KEYD  1024
#define VALD  2048
#define CDIM  4096   // 2*KEYD + VALD
#define NSEG  2
#define SEGR  (SEQ / NSEG)   // 1024 rows per segment
#define CHK   64
#define NCH   (SEQ / CHK)    // 32 chunks total
#define CHSEG (SEGR / CHK)   // 16 chunks per segment

// ------------------------------------------------------------------
// Scratch (device globals; no allocation allowed)
// ------------------------------------------------------------------
__device__ float  g_mixed[SEQ * CDIM];
__device__ float  g_qkv  [SEQ * CDIM];   // post conv+silu (q | k | v)
__device__ float2 g_eb   [SEQ * NH];     // (g, beta)  [raw log-decay]
__device__ float  g_z    [SEQ * VALD];
__device__ float  g_core [SEQ * VALD];
__device__ float  g_state[NH * 4 * 2048]; // inter-segment state slices

// chunked WY factors
__device__ float  g_W  [NCH * NH * 64 * 64];
__device__ float  g_P  [NCH * NH * 64 * 64];
__device__ float  g_Qg [NCH * NH * 64 * 64];
__device__ float  g_KcT[NCH * NH * 64 * 64];
__device__ float  g_U0 [NCH * NH * 64 * 128];
__device__ float  g_gC [NCH * NH];
__device__ float  g_Schk[NCH * NH * 4 * 2048];  // entry state per chunk
__device__ float  g_u   [SEQ * VALD];           // per-step u

__device__ __half g_hs_h  [SEQ  * HID];
__device__ __half g_Wqkv_h[CDIM * HID];
__device__ __half g_Wz_h  [VALD * HID];
__device__ __half g_Wout_h[HID  * VALD];
__device__ __half g_gat_h [SEQ  * VALD];

// ------------------------------------------------------------------
// PTX helpers
// ------------------------------------------------------------------
__device__ __forceinline__ uint32_t smem_u32(const void* p) {
    uint32_t a;
    asm("{ .reg .u64 t; cvta.to.shared.u64 t, %1; cvt.u32.u64 %0, t; }"
        : "=r"(a) : "l"(p));
    return a;
}
__device__ __forceinline__ void cp_async16(uint32_t s, const void* g) {
    asm volatile("cp.async.cg.shared.global [%0], [%1], 16;" :: "r"(s), "l"(g));
}
__device__ __forceinline__ void cp_commit() {
    asm volatile("cp.async.commit_group;");
}
template <int N>
__device__ __forceinline__ void cp_wait() {
    asm volatile("cp.async.wait_group %0;" :: "n"(N));
}
__device__ __forceinline__ void ldsm4(uint32_t& r0, uint32_t& r1,
                                      uint32_t& r2, uint32_t& r3, uint32_t a) {
    asm volatile("ldmatrix.sync.aligned.m8n8.x4.shared.b16 {%0,%1,%2,%3}, [%4];"
                 : "=r"(r0), "=r"(r1), "=r"(r2), "=r"(r3) : "r"(a));
}
__device__ __forceinline__ void mma16816(float* d, const uint32_t* a,
                                         uint32_t b0, uint32_t b1) {
    asm volatile(
        "mma.sync.aligned.m16n8k16.row.col.f32.f16.f16.f32 "
        "{%0,%1,%2,%3}, {%4,%5,%6,%7}, {%8,%9}, {%0,%1,%2,%3};"
        : "+f"(d[0]), "+f"(d[1]), "+f"(d[2]), "+f"(d[3])
        : "r"(a[0]), "r"(a[1]), "r"(a[2]), "r"(a[3]), "r"(b0), "r"(b1));
}
#define SW(off) ((off) ^ (((off) >> 3) & 0x70))

// ------------------------------------------------------------------
// fp16 NT GEMM via mma.sync (unchanged, proven)
// ------------------------------------------------------------------
#define HGEMM_SMEM (4 * 16384)

__global__ __launch_bounds__(256)
void hgemm_nt(const __half* __restrict__ A, const __half* __restrict__ B,
              float* __restrict__ C, int M, int N, int K)
{
    extern __shared__ __align__(1024) char sm[];
    const int tid  = threadIdx.x;
    const int wid  = tid >> 5, lane = tid & 31;
    const int tileN = blockIdx.x, tileM = blockIdx.y;
    const int wm = (wid >> 1) * 32;
    const int wn = (wid & 1) * 64;

    const uint32_t sbase = smem_u32(sm);
    const char* Ag = (const char*)(A + (size_t)tileM * 128 * K);
    const char* Bg = (const char*)(B + (size_t)tileN * 128 * K);
    const size_t rs = (size_t)K * 2;
    const int crow = tid >> 3;
    const int ccol = (tid & 7) * 16;

    int offA[2], offB[4];
#pragma unroll
    for (int mt = 0; mt < 2; mt++)
        offA[mt] = (wm + mt * 16 + (lane & 15)) * 128 + (lane >> 4) * 16;
#pragma unroll
    for (int j2 = 0; j2 < 4; j2++)
        offB[j2] = (wn + j2 * 16 + (lane & 7) + ((lane >> 4) & 1) * 8) * 128
                 + ((lane >> 3) & 1) * 16;

    float acc[2][8][4];
#pragma unroll
    for (int mt = 0; mt < 2; mt++)
#pragma unroll
        for (int nt = 0; nt < 8; nt++)
#pragma unroll
            for (int r = 0; r < 4; r++) acc[mt][nt][r] = 0.f;

    const int chunks = K >> 6;

#define ISSUEG(i, b)                                                         \
    do {                                                                     \
        uint32_t sA = sbase + (b) * 32768;                                   \
        uint32_t sB = sA + 16384;                                            \
        const char* gA = Ag + (size_t)(i) * 128 + ccol;                      \
        const char* gB = Bg + (size_t)(i) * 128 + ccol;                      \
        _Pragma("unroll")                                                    \
        for (int p = 0; p < 4; p++) {                                        \
            int row = crow + p * 32;                                         \
            int so  = SW(row * 128 + ccol);                                  \
            cp_async16(sA + so, gA + row * rs);                              \
            cp_async16(sB + so, gB + row * rs);                              \
        }                                                                    \
        cp_commit();                                                         \
    } while (0)

    ISSUEG(0, 0);
    for (int i = 0; i < chunks; i++) {
        const int b = i & 1;
        if (i + 1 < chunks) { ISSUEG(i + 1, b ^ 1); cp_wait<1>(); }
        else                { cp_wait<0>(); }
        __syncthreads();
        const uint32_t sA = sbase + b * 32768;
        const uint32_t sB = sA + 16384;
#pragma unroll
        for (int ks = 0; ks < 4; ks++) {
            uint32_t af[2][4];
#pragma unroll
            for (int mt = 0; mt < 2; mt++) {
                int off = offA[mt] + ks * 32;
                ldsm4(af[mt][0], af[mt][1], af[mt][2], af[mt][3], sA + SW(off));
            }
            uint32_t bf[8][2];
#pragma unroll
            for (int j2 = 0; j2 < 4; j2++) {
                int off = offB[j2] + ks * 32;
                uint32_t r0, r1, r2, r3;
                ldsm4(r0, r1, r2, r3, sB + SW(off));
                bf[2 * j2][0] = r0; bf[2 * j2][1] = r1;
                bf[2 * j2 + 1][0] = r2; bf[2 * j2 + 1][1] = r3;
            }
#pragma unroll
            for (int mt = 0; mt < 2; mt++)
#pragma unroll
                for (int nt = 0; nt < 8; nt++)
                    mma16816(acc[mt][nt], af[mt], bf[nt][0], bf[nt][1]);
        }
        __syncthreads();
    }
#undef ISSUEG

    const int gid = lane >> 2, ctg = lane & 3;
#pragma unroll
    for (int mt = 0; mt < 2; mt++) {
        int m0 = tileM * 128 + wm + mt * 16 + gid;
#pragma unroll
        for (int nt = 0; nt < 8; nt++) {
            int n0 = tileN * 128 + wn + nt * 8 + ctg * 2;
            *(float2*)(C + (size_t)m0 * N + n0) =
                make_float2(acc[mt][nt][0], acc[mt][nt][1]);
            *(float2*)(C + (size_t)(m0 + 8) * N + n0) =
                make_float2(acc[mt][nt][2], acc[mt][nt][3]);
        }
    }
}

// ------------------------------------------------------------------
// fp32 -> fp16, 8 elems/thread.
// ------------------------------------------------------------------
__global__ __launch_bounds__(256)
void f2h_kernel(const float* __restrict__ in, __half* __restrict__ out)
{
    int idx = (blockIdx.x * 256 + threadIdx.x) * 8;
    float4 x0 = *(const float4*)(in + idx);
    float4 x1 = *(const float4*)(in + idx + 4);
    union { __half2 h[4]; uint4 u; } r;
    r.h[0] = __floats2half2_rn(x0.x, x0.y);
    r.h[1] = __floats2half2_rn(x0.z, x0.w);
    r.h[2] = __floats2half2_rn(x1.x, x1.y);
    r.h[3] = __floats2half2_rn(x1.z, x1.w);
    *(uint4*)(out + idx) = r.u;
}

// ------------------------------------------------------------------
// Fused conv(K=4)+SiLU+l2norm over one row segment (unchanged).
// ------------------------------------------------------------------
__global__ __launch_bounds__(512)
void conv_norm_seg(const float* __restrict__ mixed,
                   const float* __restrict__ w,
                   float* __restrict__ qkv, int row0)
{
    const int t  = row0 + blockIdx.x;
    const int c0 = threadIdx.x * 8;
    const size_t idx = (size_t)t * CDIM + c0;

    float x[8];
    {
        float4 a0 = *(const float4*)(mixed + idx);
        float4 a1 = *(const float4*)(mixed + idx + 4);
        float xs[8] = {a0.x, a0.y, a0.z, a0.w, a1.x, a1.y, a1.z, a1.w};
        float p1[8] = {0}, p2[8] = {0}, p3[8] = {0};
        if (t >= 1) {
            float4 b0 = *(const float4*)(mixed + idx - CDIM);
            float4 b1 = *(const float4*)(mixed + idx - CDIM + 4);
            p1[0]=b0.x;p1[1]=b0.y;p1[2]=b0.z;p1[3]=b0.w;p1[4]=b1.x;p1[5]=b1.y;p1[6]=b1.z;p1[7]=b1.w;
        }
        if (t >= 2) {
            float4 b0 = *(const float4*)(mixed + idx - 2 * CDIM);
            float4 b1 = *(const float4*)(mixed + idx - 2 * CDIM + 4);
            p2[0]=b0.x;p2[1]=b0.y;p2[2]=b0.z;p2[3]=b0.w;p2[4]=b1.x;p2[5]=b1.y;p2[6]=b1.z;p2[7]=b1.w;
        }
        if (t >= 3) {
            float4 b0 = *(const float4*)(mixed + idx - 3 * CDIM);
            float4 b1 = *(const float4*)(mixed + idx - 3 * CDIM + 4);
            p3[0]=b0.x;p3[1]=b0.y;p3[2]=b0.z;p3[3]=b0.w;p3[4]=b1.x;p3[5]=b1.y;p3[6]=b1.z;p3[7]=b1.w;
        }
#pragma unroll
        for (int j = 0; j < 8; j++) {
            float4 wj = *(const float4*)(w + (c0 + j) * 4);
            float acc = wj.w * xs[j];
            acc = fmaf(wj.z, p1[j], acc);
            acc = fmaf(wj.y, p2[j], acc);
            acc = fmaf(wj.x, p3[j], acc);
            x[j] = acc / (1.f + expf(-acc));
        }
    }
    if (c0 < 2 * KEYD) {
        float ss = 0.f;
#pragma unroll
        for (int j = 0; j < 8; j++) ss += x[j] * x[j];
        ss += __shfl_xor_sync(0xffffffffu, ss, 1);
        ss += __shfl_xor_sync(0xffffffffu, ss, 2);
        ss += __shfl_xor_sync(0xffffffffu, ss, 4);
        float r = rsqrtf(ss + 1e-6f);
        if (c0 < KEYD) r *= 0.125f;
#pragma unroll
        for (int j = 0; j < 8; j++) x[j] *= r;
    }
    *(float4*)(qkv + idx)     = make_float4(x[0], x[1], x[2], x[3]);
    *(float4*)(qkv + idx + 4) = make_float4(x[4], x[5], x[6], x[7]);
}

// ------------------------------------------------------------------
// a/b projections -> (g, beta).   g = raw log-decay.
// ------------------------------------------------------------------
__global__ __launch_bounds__(256)
void ab_kernel(const float* __restrict__ hs,
               const float* __restrict__ Wa,
               const float* __restrict__ Wb,
               const float* __restrict__ A_log,
               const float* __restrict__ dt_bias,
               float2* __restrict__ eb)
{
    int w    = blockIdx.x * (blockDim.x >> 5) + (threadIdx.x >> 5);
    int lane = threadIdx.x & 31;
    if (w >= SEQ * NH) return;
    int t = w >> 4, h = w & 15;

    const float4* x4 = (const float4*)(hs + (size_t)t * HID);
    const float4* a4 = (const float4*)(Wa + (size_t)h * HID);
    const float4* b4 = (const float4*)(Wb + (size_t)h * HID);

    float sa = 0.f, sb = 0.f;
    for (int i = lane; i < HID / 4; i += 32) {
        float4 x = x4[i], a = a4[i], b = b4[i];
        sa += x.x * a.x + x.y * a.y + x.z * a.z + x.w * a.w;
        sb += x.x * b.x + x.y * b.y + x.z * b.z + x.w * b.w;
    }
#pragma unroll
    for (int o = 16; o; o >>= 1) {
        sa += __shfl_xor_sync(0xffffffffu, sa, o);
        sb += __shfl_xor_sync(0xffffffffu, sb, o);
    }
    if (lane == 0) {
        float av = sa + dt_bias[h];
        float sp = (av > 20.f) ? av : log1pf(expf(av));
        eb[t * NH + h] = make_float2(-expf(A_log[h]) * sp,
                                     1.f / (1.f + expf(-sb)));
    }
}

// ------------------------------------------------------------------
// Phase 1: per-chunk WY factors (unchanged from R10).
// ------------------------------------------------------------------
#define PREP_SMEM ((4 * 64 * 68 + 64 * 132 + 3 * 64) * 4)

__global__ __launch_bounds__(256)
void chunk_prep(const float* __restrict__ qkv,
                const float2* __restrict__ eb,
                float* __restrict__ Wg,  float* __restrict__ Pg,
                float* __restrict__ Qgg, float* __restrict__ KcTg,
                float* __restrict__ U0g, float* __restrict__ gCg,
                int c0)
{
    const int c = c0 + blockIdx.x;
    const int h = blockIdx.y;
    const int tid = threadIdx.x;
    const int t0 = c * CHK;

    extern __shared__ float smp[];
    float* Ks  = smp;                // [64][68]
    float* Qs  = Ks  + 64 * 68;
    float* Ms  = Qs  + 64 * 68;
    float* Ts  = Ms  + 64 * 68;
    float* Vs  = Ts  + 64 * 68;     // [64][132]
    float* lg  = Vs  + 64 * 132;
    float* bet = lg  + 64;
    float* sK  = bet + 64;

    for (int i = tid; i < 64 * 16; i += 256) {
        int r = i >> 4, j4 = i & 15;
        const float* row = qkv + (size_t)(t0 + r) * CDIM;
        *(float4*)&Qs[r * 68 + j4 * 4] = *(const float4*)(row + h * 64 + j4 * 4);
        *(float4*)&Ks[r * 68 + j4 * 4] = *(const float4*)(row + KEYD + h * 64 + j4 * 4);
    }
    for (int i = tid; i < 64 * 32; i += 256) {
        int r = i >> 5, j4 = i & 31;
        const float* row = qkv + (size_t)(t0 + r) * CDIM;
        *(float4*)&Vs[r * 132 + j4 * 4] = *(const float4*)(row + 2 * KEYD + h * DV + j4 * 4);
    }
    if (tid < 64) {
        float2 e = eb[(t0 + tid) * NH + h];
        lg[tid]  = e.x;
        bet[tid] = e.y;
    }
    __syncthreads();
    if (tid == 0) {
        float a = 0.f;
        for (int t = 0; t < 64; t++) { a += lg[t]; lg[t] = a; }
    }
    __syncthreads();

    {
        const int t  = tid >> 2;
        const int sb = (tid & 3) * 16;
        float ak[16], aq[16];
#pragma unroll
        for (int i = 0; i < 16; i++) { ak[i] = 0.f; aq[i] = 0.f; }
        for (int jb = 0; jb < 16; jb++) {
            float4 kt = *(const float4*)&Ks[t * 68 + jb * 4];
            float4 qt = *(const float4*)&Qs[t * 68 + jb * 4];
#pragma unroll
            for (int si = 0; si < 16; si++) {
                float4 ks = *(const float4*)&Ks[(sb + si) * 68 + jb * 4];
                ak[si] += kt.x * ks.x + kt.y * ks.y + kt.z * ks.z + kt.w * ks.w;
                aq[si] += qt.x * ks.x + qt.y * ks.y + qt.z * ks.z + qt.w * ks.w;
            }
        }
        float lgt = lg[t], bt = bet[t];
        float* Pout = Pg + ((size_t)(c * NH + h) << 12);
#pragma unroll
        for (int si = 0; si < 16; si++) {
            int s = sb + si;
            float rr = expf(lgt - lg[s]);
            Ms[t * 68 + s]  = (s < t)  ? bt * rr * ak[si] : 0.f;
            Pout[t * 64 + s] = (s <= t) ? rr * aq[si] : 0.f;
        }
    }
    __syncthreads();

    if (tid < 64) {
        const int cc = tid;
        for (int i = 0; i < 64; i++) {
            float acc = (i == cc) ? 1.f : 0.f;
            for (int j = 0; j < i; j++)
                acc -= Ms[i * 68 + j] * Ts[j * 68 + cc];
            Ts[i * 68 + cc] = acc;
        }
        sK[cc] = bet[cc] * expf(lg[cc]);
    } else {
        float lgC = lg[63];
        float* Qout = Qgg  + ((size_t)(c * NH + h) << 12);
        float* Kout = KcTg + ((size_t)(c * NH + h) << 12);
        for (int i = tid - 64; i < 4096; i += 192) {
            int t = i >> 6, d_ = i & 63;
            Qout[i] = expf(lg[t]) * Qs[t * 68 + d_];
            Kout[i] = expf(lgC - lg[d_]) * Ks[d_ * 68 + t];
        }
        if (tid == 64) gCg[c * NH + h] = expf(lgC);
    }
    __syncthreads();

    {
        const int t  = tid >> 2;
        const int db = (tid & 3) * 16;
        float acc[16];
#pragma unroll
        for (int i = 0; i < 16; i++) acc[i] = 0.f;
        for (int j = 0; j < 64; j++) {
            float m = Ts[t * 68 + j] * sK[j];
#pragma unroll
            for (int i4 = 0; i4 < 4; i4++) {
                float4 kv = *(const float4*)&Ks[j * 68 + db + i4 * 4];
                acc[i4 * 4 + 0] = fmaf(m, kv.x, acc[i4 * 4 + 0]);
                acc[i4 * 4 + 1] = fmaf(m, kv.y, acc[i4 * 4 + 1]);
                acc[i4 * 4 + 2] = fmaf(m, kv.z, acc[i4 * 4 + 2]);
                acc[i4 * 4 + 3] = fmaf(m, kv.w, acc[i4 * 4 + 3]);
            }
        }
        float* Wout = Wg + ((size_t)(c * NH + h) << 12);
#pragma unroll
        for (int i4 = 0; i4 < 4; i4++)
            *(float4*)&Wout[t * 64 + db + i4 * 4] =
                make_float4(acc[i4*4], acc[i4*4+1], acc[i4*4+2], acc[i4*4+3]);
    }
    {
        const int t  = tid >> 2;
        const int db = (tid & 3) * 32;
        float acc[32];
#pragma unroll
        for (int i = 0; i < 32; i++) acc[i] = 0.f;
        for (int j = 0; j < 64; j++) {
            float m = Ts[t * 68 + j] * bet[j];
#pragma unroll
            for (int i4 = 0; i4 < 8; i4++) {
                float4 vv = *(const float4*)&Vs[j * 132 + db + i4 * 4];
                acc[i4 * 4 + 0] = fmaf(m, vv.x, acc[i4 * 4 + 0]);
                acc[i4 * 4 + 1] = fmaf(m, vv.y, acc[i4 * 4 + 1]);
                acc[i4 * 4 + 2] = fmaf(m, vv.z, acc[i4 * 4 + 2]);
                acc[i4 * 4 + 3] = fmaf(m, vv.w, acc[i4 * 4 + 3]);
            }
        }
        float* Uout = U0g + ((size_t)(c * NH + h) << 13);
#pragma unroll
        for (int i4 = 0; i4 < 8; i4++)
            *(float4*)&Uout[t * 128 + db + i4 * 4] =
                make_float4(acc[i4*4], acc[i4*4+1], acc[i4*4+2], acc[i4*4+3]);
    }
}

// ------------------------------------------------------------------
// Phase 2a (SEQUENTIAL): state propagation only.
//   u = U0 - W S ; store S_entry, u ; S = gC S + KcT u.
// Grid (4, NH), 256 threads. CTA owns (head h, DV slice of 32).
// ------------------------------------------------------------------
#define STATE_SMEM ((2 * 64 * 68 + 2 * 64 * 33) * 4)

__global__ __launch_bounds__(256)
void chunk_state(const float* __restrict__ Wg, const float* __restrict__ KcTg,
                 const float* __restrict__ U0g, const float* __restrict__ gCg,
                 float* __restrict__ Schk, float* __restrict__ ug,
                 float* __restrict__ state, int c0, int nch)
{
    const int dvs = blockIdx.x;
    const int h   = blockIdx.y;
    const int tid = threadIdx.x;
    const int d   = tid & 31;
    const int tt  = tid >> 5;

    extern __shared__ float sms[];
    float* Ws  = sms;               // [64][68]
    float* Kts = Ws  + 64 * 68;
    float* Ss  = Kts + 64 * 68;     // [64][33]
    float* us  = Ss  + 64 * 33;

    float* stbase = state + (size_t)(h * 4 + dvs) * 2048;

    if (c0 == 0) {
#pragma unroll
        for (int r = 0; r < 8; r++) Ss[(tt * 8 + r) * 33 + d] = 0.f;
    } else {
#pragma unroll
        for (int r = 0; r < 8; r++)
            Ss[(tt * 8 + r) * 33 + d] = stbase[(tt * 8 + r) * 32 + d];
    }
    __syncthreads();

    for (int cc = 0; cc < nch; cc++) {
        const int cidx = c0 + cc;
        const size_t b4k = (size_t)(cidx * NH + h) << 12;
        for (int i = tid; i < 1024; i += 256) {
            int r = i >> 4, c4 = (i & 15) * 4;
            *(float4*)&Ws [r * 68 + c4] = *(const float4*)(Wg   + b4k + i * 4);
            *(float4*)&Kts[r * 68 + c4] = *(const float4*)(KcTg + b4k + i * 4);
        }
        float gC = gCg[cidx * NH + h];
        __syncthreads();

        // store entry state
        float* Sb = Schk + ((size_t)(cidx * NH + h) * 4 + dvs) * 2048;
#pragma unroll
        for (int r = 0; r < 8; r++)
            Sb[(tt * 8 + r) * 32 + d] = Ss[(tt * 8 + r) * 33 + d];

        // u = U0 - W S
        const float* U0p = U0g + ((size_t)(cidx * NH + h) << 13) + dvs * 32 + d;
        float uacc[8];
#pragma unroll
        for (int r = 0; r < 8; r++) uacc[r] = U0p[(tt * 8 + r) * 128];
        for (int jb = 0; jb < 16; jb++) {
            float s0 = Ss[(jb * 4 + 0) * 33 + d];
            float s1 = Ss[(jb * 4 + 1) * 33 + d];
            float s2 = Ss[(jb * 4 + 2) * 33 + d];
            float s3 = Ss[(jb * 4 + 3) * 33 + d];
#pragma unroll
            for (int r = 0; r < 8; r++) {
                float4 wv = *(const float4*)&Ws[(tt * 8 + r) * 68 + jb * 4];
                uacc[r] -= wv.x * s0 + wv.y * s1 + wv.z * s2 + wv.w * s3;
            }
        }
        float* ub = ug + (size_t)(cidx * CHK) * VALD + h * DV + dvs * 32 + d;
#pragma unroll
        for (int r = 0; r < 8; r++) {
            us[(tt * 8 + r) * 33 + d] = uacc[r];
            ub[(size_t)(tt * 8 + r) * VALD] = uacc[r];
        }
        __syncthreads();

        // S' = gC S + KcT u
        float sacc[8];
#pragma unroll
        for (int r = 0; r < 8; r++) sacc[r] = gC * Ss[(tt * 8 + r) * 33 + d];
        for (int sb = 0; sb < 16; sb++) {
            float u0 = us[(sb*4+0)*33 + d], u1 = us[(sb*4+1)*33 + d];
            float u2 = us[(sb*4+2)*33 + d], u3 = us[(sb*4+3)*33 + d];
#pragma unroll
            for (int r = 0; r < 8; r++) {
                float4 kv = *(const float4*)&Kts[(tt * 8 + r) * 68 + sb * 4];
                sacc[r] += kv.x * u0 + kv.y * u1 + kv.z * u2 + kv.w * u3;
            }
        }
        __syncthreads();
#pragma unroll
        for (int r = 0; r < 8; r++) Ss[(tt * 8 + r) * 33 + d] = sacc[r];
        __syncthreads();
    }
#pragma unroll
    for (int r = 0; r < 8; r++)
        stbase[(tt * 8 + r) * 32 + d] = Ss[(tt * 8 + r) * 33 + d];
}

// ------------------------------------------------------------------
// Phase 2b (PARALLEL): O = Qg S + P u per chunk.
// Grid (CHSEG*4, NH): c = c0 + bx>>2, dvs = bx&3.
// ------------------------------------------------------------------
#define OUT_SMEM ((2 * 64 * 68 + 2 * 64 * 33) * 4)

__global__ __launch_bounds__(256)
void chunk_out(const float* __restrict__ Pg, const float* __restrict__ Qgg,
               const float* __restrict__ Schk, const float* __restrict__ ug,
               float* __restrict__ core, int c0)
{
    const int cidx = c0 + (blockIdx.x >> 2);
    const int dvs  = blockIdx.x & 3;
    const int h    = blockIdx.y;
    const int tid  = threadIdx.x;
    const int d    = tid & 31;
    const int tt   = tid >> 5;

    extern __shared__ float smo[];
    float* Qgs = smo;               // [64][68]
    float* Ps  = Qgs + 64 * 68;
    float* Ss  = Ps  + 64 * 68;     // [64][33]
    float* us  = Ss  + 64 * 33;

    const size_t b4k = (size_t)(cidx * NH + h) << 12;
    for (int i = tid; i < 1024; i += 256) {
        int r = i >> 4, c4 = (i & 15) * 4;
        *(float4*)&Qgs[r * 68 + c4] = *(const float4*)(Qgg + b4k + i * 4);
        *(float4*)&Ps [r * 68 + c4] = *(const float4*)(Pg  + b4k + i * 4);
    }
    const float* Sb = Schk + ((size_t)(cidx * NH + h) * 4 + dvs) * 2048;
    const float* ub = ug + (size_t)(cidx * CHK) * VALD + h * DV + dvs * 32 + d;
#pragma unroll
    for (int r = 0; r < 8; r++) {
        Ss[(tt * 8 + r) * 33 + d] = Sb[(tt * 8 + r) * 32 + d];
        us[(tt * 8 + r) * 33 + d] = ub[(size_t)(tt * 8 + r) * VALD];
    }
    __syncthreads();

    float oacc[8];
#pragma unroll
    for (int r = 0; r < 8; r++) oacc[r] = 0.f;
    for (int jb = 0; jb < 16; jb++) {
        float s0 = Ss[(jb*4+0)*33 + d], s1 = Ss[(jb*4+1)*33 + d];
        float s2 = Ss[(jb*4+2)*33 + d], s3 = Ss[(jb*4+3)*33 + d];
        float u0 = us[(jb*4+0)*33 + d], u1 = us[(jb*4+1)*33 + d];
        float u2 = us[(jb*4+2)*33 + d], u3 = us[(jb*4+3)*33 + d];
#pragma unroll
        for (int r = 0; r < 8; r++) {
            float4 qv = *(const float4*)&Qgs[(tt * 8 + r) * 68 + jb * 4];
            float4 pv = *(const float4*)&Ps [(tt * 8 + r) * 68 + jb * 4];
            oacc[r] += qv.x * s0 + qv.y * s1 + qv.z * s2 + qv.w * s3
                     + pv.x * u0 + pv.y * u1 + pv.z * u2 + pv.w * u3;
        }
    }
    float* corep = core + (size_t)(cidx * CHK) * VALD + h * DV + dvs * 32 + d;
#pragma unroll
    for (int r = 0; r < 8; r++)
        corep[(size_t)(tt * 8 + r) * VALD] = oacc[r];
}

// ------------------------------------------------------------------
// Gated RMSNorm + SiLU(z), fp16 output, per row segment.
// ------------------------------------------------------------------
__global__ __launch_bounds__(256)
void gate_norm_seg(const float* __restrict__ core,
                   const float* __restrict__ z,
                   const float* __restrict__ norm_w,
                   __half* __restrict__ out, int w0)
{
    int w    = w0 + blockIdx.x * (blockDim.x >> 5) + (threadIdx.x >> 5);
    int lane = threadIdx.x & 31;
    int t = w >> 4, h = w & 15;
    size_t base = (size_t)t * VALD + h * DV;

    float4 cv = ((const float4*)(core + base))[lane];
    float ss = cv.x * cv.x + cv.y * cv.y + cv.z * cv.z + cv.w * cv.w;
#pragma unroll
    for (int o = 16; o; o >>= 1) ss += __shfl_xor_sync(0xffffffffu, ss, o);
    float r = rsqrtf(ss * (1.f / DV) + 1e-6f);

    float4 zv = ((const float4*)(z + base))[lane];
    float4 nw = ((const float4*)norm_w)[lane];
    float v0 = cv.x * r * nw.x * (zv.x / (1.f + expf(-zv.x)));
    float v1 = cv.y * r * nw.y * (zv.y / (1.f + expf(-zv.y)));
    float v2 = cv.z * r * nw.z * (zv.z / (1.f + expf(-zv.z)));
    float v3 = cv.w * r * nw.w * (zv.w / (1.f + expf(-zv.w)));

    union { __half2 h2[2]; uint2 u; } o2;
    o2.h2[0] = __floats2half2_rn(v0, v1);
    o2.h2[1] = __floats2half2_rn(v2, v3);
    *(uint2*)(out + base + lane * 4) = o2.u;
}

// ------------------------------------------------------------------
// Launch: 4-stream pipeline over 2 segments.
// ------------------------------------------------------------------
static cudaStream_t g_sP = nullptr, g_sS = nullptr, g_sT = nullptr;
static cudaEvent_t  g_evFork, g_evHs, g_evAB, g_evEnd;
static cudaEvent_t  g_evQ[NSEG], g_evP[NSEG], g_evS[NSEG];

extern "C" void kernel_launch(void* const* d_in, const int* in_sizes, int n_in,
                              void* d_out, int out_size)
{
    const float* hs      = (const float*)d_in[0];
    const float* Wqkv    = (const float*)d_in[1];
    const float* Wa      = (const float*)d_in[2];
    const float* Wb      = (const float*)d_in[3];
    const float* Wz      = (const float*)d_in[4];
    const float* convw   = (const float*)d_in[5];
    const float* A_log   = (const float*)d_in[6];
    const float* dt_bias = (const float*)d_in[7];
    const float* norm_w  = (const float*)d_in[8];
    const float* Wout    = (const float*)d_in[9];
    float* out = (float*)d_out;

    if (!g_sS) {
        cudaStreamCreateWithFlags(&g_sP, cudaStreamNonBlocking);
        cudaStreamCreateWithFlags(&g_sS, cudaStreamNonBlocking);
        cudaStreamCreateWithFlags(&g_sT, cudaStreamNonBlocking);
        cudaEventCreateWithFlags(&g_evFork, cudaEventDisableTiming);
        cudaEventCreateWithFlags(&g_evHs,   cudaEventDisableTiming);
        cudaEventCreateWithFlags(&g_evAB,   cudaEventDisableTiming);
        cudaEventCreateWithFlags(&g_evEnd,  cudaEventDisableTiming);
        for (int b = 0; b < NSEG; b++) {
            cudaEventCreateWithFlags(&g_evQ[b], cudaEventDisableTiming);
            cudaEventCreateWithFlags(&g_evP[b], cudaEventDisableTiming);
            cudaEventCreateWithFlags(&g_evS[b], cudaEventDisableTiming);
        }
        cudaFuncSetAttribute(hgemm_nt,
                             cudaFuncAttributeMaxDynamicSharedMemorySize, HGEMM_SMEM);
        cudaFuncSetAttribute(chunk_prep,
                             cudaFuncAttributeMaxDynamicSharedMemorySize, PREP_SMEM);
        cudaFuncSetAttribute(chunk_state,
                             cudaFuncAttributeMaxDynamicSharedMemorySize, STATE_SMEM);
        cudaFuncSetAttribute(chunk_out,
                             cudaFuncAttributeMaxDynamicSharedMemorySize, OUT_SMEM);
    }

    float  *p_mixed, *p_qkv, *p_z, *p_core, *p_state, *p_Schk, *p_u;
    float  *p_W, *p_P, *p_Qg, *p_KcT, *p_U0, *p_gC;
    float2 *p_eb;
    __half *p_hs, *p_Wqkv, *p_Wz, *p_Wout, *p_gat;
    cudaGetSymbolAddress((void**)&p_mixed, g_mixed);
    cudaGetSymbolAddress((void**)&p_qkv,   g_qkv);
    cudaGetSymbolAddress((void**)&p_eb,    g_eb);
    cudaGetSymbolAddress((void**)&p_z,     g_z);
    cudaGetSymbolAddress((void**)&p_core,  g_core);
    cudaGetSymbolAddress((void**)&p_state, g_state);
    cudaGetSymbolAddress((void**)&p_Schk,  g_Schk);
    cudaGetSymbolAddress((void**)&p_u,     g_u);
    cudaGetSymbolAddress((void**)&p_W,     g_W);
    cudaGetSymbolAddress((void**)&p_P,     g_P);
    cudaGetSymbolAddress((void**)&p_Qg,    g_Qg);
    cudaGetSymbolAddress((void**)&p_KcT,   g_KcT);
    cudaGetSymbolAddress((void**)&p_U0,    g_U0);
    cudaGetSymbolAddress((void**)&p_gC,    g_gC);
    cudaGetSymbolAddress((void**)&p_hs,    g_hs_h);
    cudaGetSymbolAddress((void**)&p_Wqkv,  g_Wqkv_h);
    cudaGetSymbolAddress((void**)&p_Wz,    g_Wz_h);
    cudaGetSymbolAddress((void**)&p_Wout,  g_Wout_h);
    cudaGetSymbolAddress((void**)&p_gat,   g_gat_h);

    cudaEventRecord(g_evFork, 0);
    cudaStreamWaitEvent(g_sP, g_evFork, 0);
    cudaStreamWaitEvent(g_sS, g_evFork, 0);
    cudaStreamWaitEvent(g_sT, g_evFork, 0);

    // stream 0: conversions + segmented qkv GEMM + conv/norm
    f2h_kernel<<<(SEQ * HID / 8) / 256, 256>>>(hs, p_hs);
    cudaEventRecord(g_evHs, 0);
    f2h_kernel<<<(CDIM * HID / 8) / 256, 256>>>(Wqkv, p_Wqkv);
    for (int b = 0; b < NSEG; b++) {
        int row0 = b * SEGR;
        hgemm_nt<<<dim3(CDIM / 128, SEGR / 128), 256, HGEMM_SMEM>>>(
            p_hs + (size_t)row0 * HID, p_Wqkv,
            p_mixed + (size_t)row0 * CDIM, SEGR, CDIM, HID);
        conv_norm_seg<<<SEGR, 512>>>(p_mixed, convw, p_qkv, row0);
        cudaEventRecord(g_evQ[b], 0);
    }

    // stream T: ab, z chain, Wout conversion
    ab_kernel<<<(SEQ * NH) / 8, 256, 0, g_sT>>>(hs, Wa, Wb, A_log, dt_bias, p_eb);
    cudaEventRecord(g_evAB, g_sT);
    f2h_kernel<<<(VALD * HID / 8) / 256, 256, 0, g_sT>>>(Wz, p_Wz);
    cudaStreamWaitEvent(g_sT, g_evHs, 0);
    hgemm_nt<<<dim3(VALD / 128, SEQ / 128), 256, HGEMM_SMEM, g_sT>>>(
        p_hs, p_Wz, p_z, SEQ, VALD, HID);
    f2h_kernel<<<(HID * VALD / 8) / 256, 256, 0, g_sT>>>(Wout, p_Wout);

    // stream P: chunk prep per segment
    cudaStreamWaitEvent(g_sP, g_evAB, 0);
    for (int b = 0; b < NSEG; b++) {
        cudaStreamWaitEvent(g_sP, g_evQ[b], 0);
        chunk_prep<<<dim3(CHSEG, NH), 256, PREP_SMEM, g_sP>>>(
            p_qkv, p_eb, p_W, p_P, p_Qg, p_KcT, p_U0, p_gC, b * CHSEG);
        cudaEventRecord(g_evP[b], g_sP);
    }

    // stream S: sequential state recurrence per segment
    for (int b = 0; b < NSEG; b++) {
        cudaStreamWaitEvent(g_sS, g_evP[b], 0);
        chunk_state<<<dim3(4, NH), 256, STATE_SMEM, g_sS>>>(
            p_W, p_KcT, p_U0, p_gC, p_Schk, p_u, p_state, b * CHSEG, CHSEG);
        cudaEventRecord(g_evS[b], g_sS);
    }

    // stream T: parallel O + gate + out GEMM per segment
    for (int b = 0; b < NSEG; b++) {
        int row0 = b * SEGR;
        cudaStreamWaitEvent(g_sT, g_evS[b], 0);
        chunk_out<<<dim3(CHSEG * 4, NH), 256, OUT_SMEM, g_sT>>>(
            p_P, p_Qg, p_Schk, p_u, p_core, b * CHSEG);
        gate_norm_seg<<<(SEGR * NH) / 8, 256, 0, g_sT>>>(
            p_core, p_z, norm_w, p_gat, row0 * NH);
        hgemm_nt<<<dim3(HID / 128, SEGR / 128), 256, HGEMM_SMEM, g_sT>>>(
            p_gat + (size_t)row0 * VALD, p_Wout,
            out + (size_t)row0 * HID, SEGR, HID, VALD);
    }
    cudaEventRecord(g_evEnd, g_sT);
    cudaStreamWaitEvent(0, g_evEnd, 0);
}

// round 12
// speedup vs baseline: 3.8442x; 1.0888x over previous
#include <cuda_runtime.h>
#include <cuda_fp16.h>
#include <math.h>
#include <stdint.h>

#define SEQ   2048
#define HID   2048
#define NH    16
#define DK    64
#define DV    128
#define KEYD  1024
#define VALD  2048
#define CDIM  4096   // 2*KEYD + VALD
#define NSEG  2
#define SEGR  (SEQ / NSEG)   // 1024 rows per segment
#define CHK   64
#define NCH   (SEQ / CHK)    // 32 chunks total
#define CHSEG (SEGR / CHK)   // 16 chunks per segment

// ------------------------------------------------------------------
// Scratch (device globals; no allocation allowed)
// ------------------------------------------------------------------
__device__ float  g_mixed[SEQ * CDIM];
__device__ float  g_qkv  [SEQ * CDIM];   // post conv+silu (q | k | v)
__device__ float2 g_eb   [SEQ * NH];     // (g, beta)  [raw log-decay]
__device__ float  g_z    [SEQ * VALD];
__device__ float  g_core [SEQ * VALD];
__device__ float  g_state[NH * 8 * 1024]; // inter-segment state slices

// chunked WY factors
__device__ float  g_W  [NCH * NH * 64 * 64];
__device__ float  g_P  [NCH * NH * 64 * 64];
__device__ float  g_Qg [NCH * NH * 64 * 64];
__device__ float  g_KcT[NCH * NH * 64 * 64];
__device__ float  g_U0 [NCH * NH * 64 * 128];
__device__ float  g_gC [NCH * NH];
__device__ float  g_Schk[NCH * NH * 8 * 1024];  // entry state per chunk
__device__ float  g_u   [SEQ * VALD];           // per-step u

__device__ __half g_hs_h  [SEQ  * HID];
__device__ __half g_Wqkv_h[CDIM * HID];
__device__ __half g_Wz_h  [VALD * HID];
__device__ __half g_Wout_h[HID  * VALD];
__device__ __half g_gat_h [SEQ  * VALD];

// ------------------------------------------------------------------
// PTX helpers
// ------------------------------------------------------------------
__device__ __forceinline__ uint32_t smem_u32(const void* p) {
    uint32_t a;
    asm("{ .reg .u64 t; cvta.to.shared.u64 t, %1; cvt.u32.u64 %0, t; }"
        : "=r"(a) : "l"(p));
    return a;
}
__device__ __forceinline__ void cp_async16(uint32_t s, const void* g) {
    asm volatile("cp.async.cg.shared.global [%0], [%1], 16;" :: "r"(s), "l"(g));
}
__device__ __forceinline__ void cp_commit() {
    asm volatile("cp.async.commit_group;");
}
template <int N>
__device__ __forceinline__ void cp_wait() {
    asm volatile("cp.async.wait_group %0;" :: "n"(N));
}
__device__ __forceinline__ void ldsm4(uint32_t& r0, uint32_t& r1,
                                      uint32_t& r2, uint32_t& r3, uint32_t a) {
    asm volatile("ldmatrix.sync.aligned.m8n8.x4.shared.b16 {%0,%1,%2,%3}, [%4];"
                 : "=r"(r0), "=r"(r1), "=r"(r2), "=r"(r3) : "r"(a));
}
__device__ __forceinline__ void mma16816(float* d, const uint32_t* a,
                                         uint32_t b0, uint32_t b1) {
    asm volatile(
        "mma.sync.aligned.m16n8k16.row.col.f32.f16.f16.f32 "
        "{%0,%1,%2,%3}, {%4,%5,%6,%7}, {%8,%9}, {%0,%1,%2,%3};"
        : "+f"(d[0]), "+f"(d[1]), "+f"(d[2]), "+f"(d[3])
        : "r"(a[0]), "r"(a[1]), "r"(a[2]), "r"(a[3]), "r"(b0), "r"(b1));
}
#define SW(off) ((off) ^ (((off) >> 3) & 0x70))

// ------------------------------------------------------------------
// fp16 NT GEMM via mma.sync (unchanged, proven)
// ------------------------------------------------------------------
#define HGEMM_SMEM (4 * 16384)

__global__ __launch_bounds__(256)
void hgemm_nt(const __half* __restrict__ A, const __half* __restrict__ B,
              float* __restrict__ C, int M, int N, int K)
{
    extern __shared__ __align__(1024) char sm[];
    const int tid  = threadIdx.x;
    const int wid  = tid >> 5, lane = tid & 31;
    const int tileN = blockIdx.x, tileM = blockIdx.y;
    const int wm = (wid >> 1) * 32;
    const int wn = (wid & 1) * 64;

    const uint32_t sbase = smem_u32(sm);
    const char* Ag = (const char*)(A + (size_t)tileM * 128 * K);
    const char* Bg = (const char*)(B + (size_t)tileN * 128 * K);
    const size_t rs = (size_t)K * 2;
    const int crow = tid >> 3;
    const int ccol = (tid & 7) * 16;

    int offA[2], offB[4];
#pragma unroll
    for (int mt = 0; mt < 2; mt++)
        offA[mt] = (wm + mt * 16 + (lane & 15)) * 128 + (lane >> 4) * 16;
#pragma unroll
    for (int j2 = 0; j2 < 4; j2++)
        offB[j2] = (wn + j2 * 16 + (lane & 7) + ((lane >> 4) & 1) * 8) * 128
                 + ((lane >> 3) & 1) * 16;

    float acc[2][8][4];
#pragma unroll
    for (int mt = 0; mt < 2; mt++)
#pragma unroll
        for (int nt = 0; nt < 8; nt++)
#pragma unroll
            for (int r = 0; r < 4; r++) acc[mt][nt][r] = 0.f;

    const int chunks = K >> 6;

#define ISSUEG(i, b)                                                         \
    do {                                                                     \
        uint32_t sA = sbase + (b) * 32768;                                   \
        uint32_t sB = sA + 16384;                                            \
        const char* gA = Ag + (size_t)(i) * 128 + ccol;                      \
        const char* gB = Bg + (size_t)(i) * 128 + ccol;                      \
        _Pragma("unroll")                                                    \
        for (int p = 0; p < 4; p++) {                                        \
            int row = crow + p * 32;                                         \
            int so  = SW(row * 128 + ccol);                                  \
            cp_async16(sA + so, gA + row * rs);                              \
            cp_async16(sB + so, gB + row * rs);                              \
        }                                                                    \
        cp_commit();                                                         \
    } while (0)

    ISSUEG(0, 0);
    for (int i = 0; i < chunks; i++) {
        const int b = i & 1;
        if (i + 1 < chunks) { ISSUEG(i + 1, b ^ 1); cp_wait<1>(); }
        else                { cp_wait<0>(); }
        __syncthreads();
        const uint32_t sA = sbase + b * 32768;
        const uint32_t sB = sA + 16384;
#pragma unroll
        for (int ks = 0; ks < 4; ks++) {
            uint32_t af[2][4];
#pragma unroll
            for (int mt = 0; mt < 2; mt++) {
                int off = offA[mt] + ks * 32;
                ldsm4(af[mt][0], af[mt][1], af[mt][2], af[mt][3], sA + SW(off));
            }
            uint32_t bf[8][2];
#pragma unroll
            for (int j2 = 0; j2 < 4; j2++) {
                int off = offB[j2] + ks * 32;
                uint32_t r0, r1, r2, r3;
                ldsm4(r0, r1, r2, r3, sB + SW(off));
                bf[2 * j2][0] = r0; bf[2 * j2][1] = r1;
                bf[2 * j2 + 1][0] = r2; bf[2 * j2 + 1][1] = r3;
            }
#pragma unroll
            for (int mt = 0; mt < 2; mt++)
#pragma unroll
                for (int nt = 0; nt < 8; nt++)
                    mma16816(acc[mt][nt], af[mt], bf[nt][0], bf[nt][1]);
        }
        __syncthreads();
    }
#undef ISSUEG

    const int gid = lane >> 2, ctg = lane & 3;
#pragma unroll
    for (int mt = 0; mt < 2; mt++) {
        int m0 = tileM * 128 + wm + mt * 16 + gid;
#pragma unroll
        for (int nt = 0; nt < 8; nt++) {
            int n0 = tileN * 128 + wn + nt * 8 + ctg * 2;
            *(float2*)(C + (size_t)m0 * N + n0) =
                make_float2(acc[mt][nt][0], acc[mt][nt][1]);
            *(float2*)(C + (size_t)(m0 + 8) * N + n0) =
                make_float2(acc[mt][nt][2], acc[mt][nt][3]);
        }
    }
}

// ------------------------------------------------------------------
// fp32 -> fp16, 8 elems/thread.
// ------------------------------------------------------------------
__global__ __launch_bounds__(256)
void f2h_kernel(const float* __restrict__ in, __half* __restrict__ out)
{
    int idx = (blockIdx.x * 256 + threadIdx.x) * 8;
    float4 x0 = *(const float4*)(in + idx);
    float4 x1 = *(const float4*)(in + idx + 4);
    union { __half2 h[4]; uint4 u; } r;
    r.h[0] = __floats2half2_rn(x0.x, x0.y);
    r.h[1] = __floats2half2_rn(x0.z, x0.w);
    r.h[2] = __floats2half2_rn(x1.x, x1.y);
    r.h[3] = __floats2half2_rn(x1.z, x1.w);
    *(uint4*)(out + idx) = r.u;
}

// ------------------------------------------------------------------
// Fused conv(K=4)+SiLU+l2norm over one row segment (unchanged).
// ------------------------------------------------------------------
__global__ __launch_bounds__(512)
void conv_norm_seg(const float* __restrict__ mixed,
                   const float* __restrict__ w,
                   float* __restrict__ qkv, int row0)
{
    const int t  = row0 + blockIdx.x;
    const int c0 = threadIdx.x * 8;
    const size_t idx = (size_t)t * CDIM + c0;

    float x[8];
    {
        float4 a0 = *(const float4*)(mixed + idx);
        float4 a1 = *(const float4*)(mixed + idx + 4);
        float xs[8] = {a0.x, a0.y, a0.z, a0.w, a1.x, a1.y, a1.z, a1.w};
        float p1[8] = {0}, p2[8] = {0}, p3[8] = {0};
        if (t >= 1) {
            float4 b0 = *(const float4*)(mixed + idx - CDIM);
            float4 b1 = *(const float4*)(mixed + idx - CDIM + 4);
            p1[0]=b0.x;p1[1]=b0.y;p1[2]=b0.z;p1[3]=b0.w;p1[4]=b1.x;p1[5]=b1.y;p1[6]=b1.z;p1[7]=b1.w;
        }
        if (t >= 2) {
            float4 b0 = *(const float4*)(mixed + idx - 2 * CDIM);
            float4 b1 = *(const float4*)(mixed + idx - 2 * CDIM + 4);
            p2[0]=b0.x;p2[1]=b0.y;p2[2]=b0.z;p2[3]=b0.w;p2[4]=b1.x;p2[5]=b1.y;p2[6]=b1.z;p2[7]=b1.w;
        }
        if (t >= 3) {
            float4 b0 = *(const float4*)(mixed + idx - 3 * CDIM);
            float4 b1 = *(const float4*)(mixed + idx - 3 * CDIM + 4);
            p3[0]=b0.x;p3[1]=b0.y;p3[2]=b0.z;p3[3]=b0.w;p3[4]=b1.x;p3[5]=b1.y;p3[6]=b1.z;p3[7]=b1.w;
        }
#pragma unroll
        for (int j = 0; j < 8; j++) {
            float4 wj = *(const float4*)(w + (c0 + j) * 4);
            float acc = wj.w * xs[j];
            acc = fmaf(wj.z, p1[j], acc);
            acc = fmaf(wj.y, p2[j], acc);
            acc = fmaf(wj.x, p3[j], acc);
            x[j] = acc / (1.f + expf(-acc));
        }
    }
    if (c0 < 2 * KEYD) {
        float ss = 0.f;
#pragma unroll
        for (int j = 0; j < 8; j++) ss += x[j] * x[j];
        ss += __shfl_xor_sync(0xffffffffu, ss, 1);
        ss += __shfl_xor_sync(0xffffffffu, ss, 2);
        ss += __shfl_xor_sync(0xffffffffu, ss, 4);
        float r = rsqrtf(ss + 1e-6f);
        if (c0 < KEYD) r *= 0.125f;
#pragma unroll
        for (int j = 0; j < 8; j++) x[j] *= r;
    }
    *(float4*)(qkv + idx)     = make_float4(x[0], x[1], x[2], x[3]);
    *(float4*)(qkv + idx + 4) = make_float4(x[4], x[5], x[6], x[7]);
}

// ------------------------------------------------------------------
// a/b projections -> (g, beta).   g = raw log-decay.
// ------------------------------------------------------------------
__global__ __launch_bounds__(256)
void ab_kernel(const float* __restrict__ hs,
               const float* __restrict__ Wa,
               const float* __restrict__ Wb,
               const float* __restrict__ A_log,
               const float* __restrict__ dt_bias,
               float2* __restrict__ eb)
{
    int w    = blockIdx.x * (blockDim.x >> 5) + (threadIdx.x >> 5);
    int lane = threadIdx.x & 31;
    if (w >= SEQ * NH) return;
    int t = w >> 4, h = w & 15;

    const float4* x4 = (const float4*)(hs + (size_t)t * HID);
    const float4* a4 = (const float4*)(Wa + (size_t)h * HID);
    const float4* b4 = (const float4*)(Wb + (size_t)h * HID);

    float sa = 0.f, sb = 0.f;
    for (int i = lane; i < HID / 4; i += 32) {
        float4 x = x4[i], a = a4[i], b = b4[i];
        sa += x.x * a.x + x.y * a.y + x.z * a.z + x.w * a.w;
        sb += x.x * b.x + x.y * b.y + x.z * b.z + x.w * b.w;
    }
#pragma unroll
    for (int o = 16; o; o >>= 1) {
        sa += __shfl_xor_sync(0xffffffffu, sa, o);
        sb += __shfl_xor_sync(0xffffffffu, sb, o);
    }
    if (lane == 0) {
        float av = sa + dt_bias[h];
        float sp = (av > 20.f) ? av : log1pf(expf(av));
        eb[t * NH + h] = make_float2(-expf(A_log[h]) * sp,
                                     1.f / (1.f + expf(-sb)));
    }
}

// ------------------------------------------------------------------
// Phase 1: per-chunk WY factors (unchanged from R10/R11).
// ------------------------------------------------------------------
#define PREP_SMEM ((4 * 64 * 68 + 64 * 132 + 3 * 64) * 4)

__global__ __launch_bounds__(256)
void chunk_prep(const float* __restrict__ qkv,
                const float2* __restrict__ eb,
                float* __restrict__ Wg,  float* __restrict__ Pg,
                float* __restrict__ Qgg, float* __restrict__ KcTg,
                float* __restrict__ U0g, float* __restrict__ gCg,
                int c0)
{
    const int c = c0 + blockIdx.x;
    const int h = blockIdx.y;
    const int tid = threadIdx.x;
    const int t0 = c * CHK;

    extern __shared__ float smp[];
    float* Ks  = smp;                // [64][68]
    float* Qs  = Ks  + 64 * 68;
    float* Ms  = Qs  + 64 * 68;
    float* Ts  = Ms  + 64 * 68;
    float* Vs  = Ts  + 64 * 68;     // [64][132]
    float* lg  = Vs  + 64 * 132;
    float* bet = lg  + 64;
    float* sK  = bet + 64;

    for (int i = tid; i < 64 * 16; i += 256) {
        int r = i >> 4, j4 = i & 15;
        const float* row = qkv + (size_t)(t0 + r) * CDIM;
        *(float4*)&Qs[r * 68 + j4 * 4] = *(const float4*)(row + h * 64 + j4 * 4);
        *(float4*)&Ks[r * 68 + j4 * 4] = *(const float4*)(row + KEYD + h * 64 + j4 * 4);
    }
    for (int i = tid; i < 64 * 32; i += 256) {
        int r = i >> 5, j4 = i & 31;
        const float* row = qkv + (size_t)(t0 + r) * CDIM;
        *(float4*)&Vs[r * 132 + j4 * 4] = *(const float4*)(row + 2 * KEYD + h * DV + j4 * 4);
    }
    if (tid < 64) {
        float2 e = eb[(t0 + tid) * NH + h];
        lg[tid]  = e.x;
        bet[tid] = e.y;
    }
    __syncthreads();
    if (tid == 0) {
        float a = 0.f;
        for (int t = 0; t < 64; t++) { a += lg[t]; lg[t] = a; }
    }
    __syncthreads();

    {
        const int t  = tid >> 2;
        const int sb = (tid & 3) * 16;
        float ak[16], aq[16];
#pragma unroll
        for (int i = 0; i < 16; i++) { ak[i] = 0.f; aq[i] = 0.f; }
        for (int jb = 0; jb < 16; jb++) {
            float4 kt = *(const float4*)&Ks[t * 68 + jb * 4];
            float4 qt = *(const float4*)&Qs[t * 68 + jb * 4];
#pragma unroll
            for (int si = 0; si < 16; si++) {
                float4 ks = *(const float4*)&Ks[(sb + si) * 68 + jb * 4];
                ak[si] += kt.x * ks.x + kt.y * ks.y + kt.z * ks.z + kt.w * ks.w;
                aq[si] += qt.x * ks.x + qt.y * ks.y + qt.z * ks.z + qt.w * ks.w;
            }
        }
        float lgt = lg[t], bt = bet[t];
        float* Pout = Pg + ((size_t)(c * NH + h) << 12);
#pragma unroll
        for (int si = 0; si < 16; si++) {
            int s = sb + si;
            float rr = expf(lgt - lg[s]);
            Ms[t * 68 + s]  = (s < t)  ? bt * rr * ak[si] : 0.f;
            Pout[t * 64 + s] = (s <= t) ? rr * aq[si] : 0.f;
        }
    }
    __syncthreads();

    if (tid < 64) {
        const int cc = tid;
        for (int i = 0; i < 64; i++) {
            float acc = (i == cc) ? 1.f : 0.f;
            for (int j = 0; j < i; j++)
                acc -= Ms[i * 68 + j] * Ts[j * 68 + cc];
            Ts[i * 68 + cc] = acc;
        }
        sK[cc] = bet[cc] * expf(lg[cc]);
    } else {
        float lgC = lg[63];
        float* Qout = Qgg  + ((size_t)(c * NH + h) << 12);
        float* Kout = KcTg + ((size_t)(c * NH + h) << 12);
        for (int i = tid - 64; i < 4096; i += 192) {
            int t = i >> 6, d_ = i & 63;
            Qout[i] = expf(lg[t]) * Qs[t * 68 + d_];
            Kout[i] = expf(lgC - lg[d_]) * Ks[d_ * 68 + t];
        }
        if (tid == 64) gCg[c * NH + h] = expf(lgC);
    }
    __syncthreads();

    {
        const int t  = tid >> 2;
        const int db = (tid & 3) * 16;
        float acc[16];
#pragma unroll
        for (int i = 0; i < 16; i++) acc[i] = 0.f;
        for (int j = 0; j < 64; j++) {
            float m = Ts[t * 68 + j] * sK[j];
#pragma unroll
            for (int i4 = 0; i4 < 4; i4++) {
                float4 kv = *(const float4*)&Ks[j * 68 + db + i4 * 4];
                acc[i4 * 4 + 0] = fmaf(m, kv.x, acc[i4 * 4 + 0]);
                acc[i4 * 4 + 1] = fmaf(m, kv.y, acc[i4 * 4 + 1]);
                acc[i4 * 4 + 2] = fmaf(m, kv.z, acc[i4 * 4 + 2]);
                acc[i4 * 4 + 3] = fmaf(m, kv.w, acc[i4 * 4 + 3]);
            }
        }
        float* Wout = Wg + ((size_t)(c * NH + h) << 12);
#pragma unroll
        for (int i4 = 0; i4 < 4; i4++)
            *(float4*)&Wout[t * 64 + db + i4 * 4] =
                make_float4(acc[i4*4], acc[i4*4+1], acc[i4*4+2], acc[i4*4+3]);
    }
    {
        const int t  = tid >> 2;
        const int db = (tid & 3) * 32;
        float acc[32];
#pragma unroll
        for (int i = 0; i < 32; i++) acc[i] = 0.f;
        for (int j = 0; j < 64; j++) {
            float m = Ts[t * 68 + j] * bet[j];
#pragma unroll
            for (int i4 = 0; i4 < 8; i4++) {
                float4 vv = *(const float4*)&Vs[j * 132 + db + i4 * 4];
                acc[i4 * 4 + 0] = fmaf(m, vv.x, acc[i4 * 4 + 0]);
                acc[i4 * 4 + 1] = fmaf(m, vv.y, acc[i4 * 4 + 1]);
                acc[i4 * 4 + 2] = fmaf(m, vv.z, acc[i4 * 4 + 2]);
                acc[i4 * 4 + 3] = fmaf(m, vv.w, acc[i4 * 4 + 3]);
            }
        }
        float* Uout = U0g + ((size_t)(c * NH + h) << 13);
#pragma unroll
        for (int i4 = 0; i4 < 8; i4++)
            *(float4*)&Uout[t * 128 + db + i4 * 4] =
                make_float4(acc[i4*4], acc[i4*4+1], acc[i4*4+2], acc[i4*4+3]);
    }
}

// ------------------------------------------------------------------
// Phase 2a (SEQUENTIAL): state propagation, 8-way DV split,
// cp.async double-buffered W/KcT.
// Grid (8, NH), 256 threads. d = tid&15 (16 DV cols), tt = tid>>4
// (rows tt*4 .. tt*4+3).
// ------------------------------------------------------------------
#define STATE_SMEM ((4 * 64 * 68 + 2 * 64 * 17) * 4)

__global__ __launch_bounds__(256)
void chunk_state(const float* __restrict__ Wg, const float* __restrict__ KcTg,
                 const float* __restrict__ U0g, const float* __restrict__ gCg,
                 float* __restrict__ Schk, float* __restrict__ ug,
                 float* __restrict__ state, int c0, int nch)
{
    const int dvs = blockIdx.x;       // 0..7
    const int h   = blockIdx.y;
    const int tid = threadIdx.x;
    const int d   = tid & 15;
    const int tt  = tid >> 4;         // 0..15

    extern __shared__ __align__(16) float sms[];
    // layout: W[2][4352], Kt[2][4352], Ss[1088], us[1088]
    float* Ss = sms + 4 * 4352;
    float* us = Ss + 1088;

    float* stbase = state + (size_t)(h * 8 + dvs) * 1024;

    if (c0 == 0) {
#pragma unroll
        for (int r = 0; r < 4; r++) Ss[(tt * 4 + r) * 17 + d] = 0.f;
    } else {
#pragma unroll
        for (int r = 0; r < 4; r++)
            Ss[(tt * 4 + r) * 17 + d] = stbase[(tt * 4 + r) * 16 + d];
    }

#define ISSUEWK(cidx, b)                                                   \
    do {                                                                   \
        const size_t _b4k = (size_t)((cidx) * NH + h) << 12;               \
        float* _W = sms + (b) * 4352;                                      \
        float* _K = sms + 2 * 4352 + (b) * 4352;                           \
        _Pragma("unroll")                                                  \
        for (int p = 0; p < 4; p++) {                                      \
            int i = tid + p * 256;                                         \
            int r = i >> 4, c4 = (i & 15) * 4;                             \
            cp_async16(smem_u32(&_W[r * 68 + c4]), Wg   + _b4k + i * 4);   \
            cp_async16(smem_u32(&_K[r * 68 + c4]), KcTg + _b4k + i * 4);   \
        }                                                                  \
        cp_commit();                                                       \
    } while (0)

    ISSUEWK(c0, 0);

    for (int cc = 0; cc < nch; cc++) {
        const int b = cc & 1;
        const int cidx = c0 + cc;
        if (cc + 1 < nch) { ISSUEWK(cidx + 1, b ^ 1); cp_wait<1>(); }
        else              { cp_wait<0>(); }
        __syncthreads();

        const float* Ws  = sms + b * 4352;
        const float* Kts = sms + 2 * 4352 + b * 4352;
        float gC = gCg[cidx * NH + h];

        // store entry state
        float* Sb = Schk + ((size_t)(cidx * NH + h) * 8 + dvs) * 1024;
#pragma unroll
        for (int r = 0; r < 4; r++)
            Sb[(tt * 4 + r) * 16 + d] = Ss[(tt * 4 + r) * 17 + d];

        // u = U0 - W S
        const float* U0p = U0g + ((size_t)(cidx * NH + h) << 13) + dvs * 16 + d;
        float uacc[4];
#pragma unroll
        for (int r = 0; r < 4; r++) uacc[r] = U0p[(tt * 4 + r) * 128];
        for (int jb = 0; jb < 16; jb++) {
            float s0 = Ss[(jb * 4 + 0) * 17 + d];
            float s1 = Ss[(jb * 4 + 1) * 17 + d];
            float s2 = Ss[(jb * 4 + 2) * 17 + d];
            float s3 = Ss[(jb * 4 + 3) * 17 + d];
#pragma unroll
            for (int r = 0; r < 4; r++) {
                float4 wv = *(const float4*)&Ws[(tt * 4 + r) * 68 + jb * 4];
                uacc[r] -= wv.x * s0 + wv.y * s1 + wv.z * s2 + wv.w * s3;
            }
        }
        float* ub = ug + (size_t)(cidx * CHK) * VALD + h * DV + dvs * 16 + d;
#pragma unroll
        for (int r = 0; r < 4; r++) {
            us[(tt * 4 + r) * 17 + d] = uacc[r];
            ub[(size_t)(tt * 4 + r) * VALD] = uacc[r];
        }
        __syncthreads();

        // S' = gC S + KcT u
        float sacc[4];
#pragma unroll
        for (int r = 0; r < 4; r++) sacc[r] = gC * Ss[(tt * 4 + r) * 17 + d];
        for (int sb = 0; sb < 16; sb++) {
            float u0 = us[(sb*4+0)*17 + d], u1 = us[(sb*4+1)*17 + d];
            float u2 = us[(sb*4+2)*17 + d], u3 = us[(sb*4+3)*17 + d];
#pragma unroll
            for (int r = 0; r < 4; r++) {
                float4 kv = *(const float4*)&Kts[(tt * 4 + r) * 68 + sb * 4];
                sacc[r] += kv.x * u0 + kv.y * u1 + kv.z * u2 + kv.w * u3;
            }
        }
        __syncthreads();
#pragma unroll
        for (int r = 0; r < 4; r++) Ss[(tt * 4 + r) * 17 + d] = sacc[r];
        __syncthreads();
    }
#undef ISSUEWK

#pragma unroll
    for (int r = 0; r < 4; r++)
        stbase[(tt * 4 + r) * 16 + d] = Ss[(tt * 4 + r) * 17 + d];
}

// ------------------------------------------------------------------
// Phase 2b (PARALLEL): O = Qg S + P u per chunk, 8-way DV split.
// Grid (CHSEG*8, NH).
// ------------------------------------------------------------------
#define OUT_SMEM ((2 * 64 * 68 + 2 * 64 * 17) * 4)

__global__ __launch_bounds__(256)
void chunk_out(const float* __restrict__ Pg, const float* __restrict__ Qgg,
               const float* __restrict__ Schk, const float* __restrict__ ug,
               float* __restrict__ core, int c0)
{
    const int cidx = c0 + (blockIdx.x >> 3);
    const int dvs  = blockIdx.x & 7;
    const int h    = blockIdx.y;
    const int tid  = threadIdx.x;
    const int d    = tid & 15;
    const int tt   = tid >> 4;

    extern __shared__ __align__(16) float smo[];
    float* Qgs = smo;               // [64][68]
    float* Ps  = Qgs + 64 * 68;
    float* Ss  = Ps  + 64 * 68;     // [64][17]
    float* us  = Ss  + 64 * 17;

    const size_t b4k = (size_t)(cidx * NH + h) << 12;
    for (int i = tid; i < 1024; i += 256) {
        int r = i >> 4, c4 = (i & 15) * 4;
        *(float4*)&Qgs[r * 68 + c4] = *(const float4*)(Qgg + b4k + i * 4);
        *(float4*)&Ps [r * 68 + c4] = *(const float4*)(Pg  + b4k + i * 4);
    }
    const float* Sb = Schk + ((size_t)(cidx * NH + h) * 8 + dvs) * 1024;
    const float* ub = ug + (size_t)(cidx * CHK) * VALD + h * DV + dvs * 16 + d;
#pragma unroll
    for (int r = 0; r < 4; r++) {
        Ss[(tt * 4 + r) * 17 + d] = Sb[(tt * 4 + r) * 16 + d];
        us[(tt * 4 + r) * 17 + d] = ub[(size_t)(tt * 4 + r) * VALD];
    }
    __syncthreads();

    float oacc[4];
#pragma unroll
    for (int r = 0; r < 4; r++) oacc[r] = 0.f;
    for (int jb = 0; jb < 16; jb++) {
        float s0 = Ss[(jb*4+0)*17 + d], s1 = Ss[(jb*4+1)*17 + d];
        float s2 = Ss[(jb*4+2)*17 + d], s3 = Ss[(jb*4+3)*17 + d];
        float u0 = us[(jb*4+0)*17 + d], u1 = us[(jb*4+1)*17 + d];
        float u2 = us[(jb*4+2)*17 + d], u3 = us[(jb*4+3)*17 + d];
#pragma unroll
        for (int r = 0; r < 4; r++) {
            float4 qv = *(const float4*)&Qgs[(tt * 4 + r) * 68 + jb * 4];
            float4 pv = *(const float4*)&Ps [(tt * 4 + r) * 68 + jb * 4];
            oacc[r] += qv.x * s0 + qv.y * s1 + qv.z * s2 + qv.w * s3
                     + pv.x * u0 + pv.y * u1 + pv.z * u2 + pv.w * u3;
        }
    }
    float* corep = core + (size_t)(cidx * CHK) * VALD + h * DV + dvs * 16 + d;
#pragma unroll
    for (int r = 0; r < 4; r++)
        corep[(size_t)(tt * 4 + r) * VALD] = oacc[r];
}

// ------------------------------------------------------------------
// Gated RMSNorm + SiLU(z), fp16 output, per row segment.
// ------------------------------------------------------------------
__global__ __launch_bounds__(256)
void gate_norm_seg(const float* __restrict__ core,
                   const float* __restrict__ z,
                   const float* __restrict__ norm_w,
                   __half* __restrict__ out, int w0)
{
    int w    = w0 + blockIdx.x * (blockDim.x >> 5) + (threadIdx.x >> 5);
    int lane = threadIdx.x & 31;
    int t = w >> 4, h = w & 15;
    size_t base = (size_t)t * VALD + h * DV;

    float4 cv = ((const float4*)(core + base))[lane];
    float ss = cv.x * cv.x + cv.y * cv.y + cv.z * cv.z + cv.w * cv.w;
#pragma unroll
    for (int o = 16; o; o >>= 1) ss += __shfl_xor_sync(0xffffffffu, ss, o);
    float r = rsqrtf(ss * (1.f / DV) + 1e-6f);

    float4 zv = ((const float4*)(z + base))[lane];
    float4 nw = ((const float4*)norm_w)[lane];
    float v0 = cv.x * r * nw.x * (zv.x / (1.f + expf(-zv.x)));
    float v1 = cv.y * r * nw.y * (zv.y / (1.f + expf(-zv.y)));
    float v2 = cv.z * r * nw.z * (zv.z / (1.f + expf(-zv.z)));
    float v3 = cv.w * r * nw.w * (zv.w / (1.f + expf(-zv.w)));

    union { __half2 h2[2]; uint2 u; } o2;
    o2.h2[0] = __floats2half2_rn(v0, v1);
    o2.h2[1] = __floats2half2_rn(v2, v3);
    *(uint2*)(out + base + lane * 4) = o2.u;
}

// ------------------------------------------------------------------
// Launch: 4-stream pipeline over 2 segments.
// ------------------------------------------------------------------
static cudaStream_t g_sP = nullptr, g_sS = nullptr, g_sT = nullptr;
static cudaEvent_t  g_evFork, g_evHs, g_evAB, g_evEnd;
static cudaEvent_t  g_evQ[NSEG], g_evP[NSEG], g_evS[NSEG];

extern "C" void kernel_launch(void* const* d_in, const int* in_sizes, int n_in,
                              void* d_out, int out_size)
{
    const float* hs      = (const float*)d_in[0];
    const float* Wqkv    = (const float*)d_in[1];
    const float* Wa      = (const float*)d_in[2];
    const float* Wb      = (const float*)d_in[3];
    const float* Wz      = (const float*)d_in[4];
    const float* convw   = (const float*)d_in[5];
    const float* A_log   = (const float*)d_in[6];
    const float* dt_bias = (const float*)d_in[7];
    const float* norm_w  = (const float*)d_in[8];
    const float* Wout    = (const float*)d_in[9];
    float* out = (float*)d_out;

    if (!g_sS) {
        cudaStreamCreateWithFlags(&g_sP, cudaStreamNonBlocking);
        cudaStreamCreateWithFlags(&g_sS, cudaStreamNonBlocking);
        cudaStreamCreateWithFlags(&g_sT, cudaStreamNonBlocking);
        cudaEventCreateWithFlags(&g_evFork, cudaEventDisableTiming);
        cudaEventCreateWithFlags(&g_evHs,   cudaEventDisableTiming);
        cudaEventCreateWithFlags(&g_evAB,   cudaEventDisableTiming);
        cudaEventCreateWithFlags(&g_evEnd,  cudaEventDisableTiming);
        for (int b = 0; b < NSEG; b++) {
            cudaEventCreateWithFlags(&g_evQ[b], cudaEventDisableTiming);
            cudaEventCreateWithFlags(&g_evP[b], cudaEventDisableTiming);
            cudaEventCreateWithFlags(&g_evS[b], cudaEventDisableTiming);
        }
        cudaFuncSetAttribute(hgemm_nt,
                             cudaFuncAttributeMaxDynamicSharedMemorySize, HGEMM_SMEM);
        cudaFuncSetAttribute(chunk_prep,
                             cudaFuncAttributeMaxDynamicSharedMemorySize, PREP_SMEM);
        cudaFuncSetAttribute(chunk_state,
                             cudaFuncAttributeMaxDynamicSharedMemorySize, STATE_SMEM);
        cudaFuncSetAttribute(chunk_out,
                             cudaFuncAttributeMaxDynamicSharedMemorySize, OUT_SMEM);
    }

    float  *p_mixed, *p_qkv, *p_z, *p_core, *p_state, *p_Schk, *p_u;
    float  *p_W, *p_P, *p_Qg, *p_KcT, *p_U0, *p_gC;
    float2 *p_eb;
    __half *p_hs, *p_Wqkv, *p_Wz, *p_Wout, *p_gat;
    cudaGetSymbolAddress((void**)&p_mixed, g_mixed);
    cudaGetSymbolAddress((void**)&p_qkv,   g_qkv);
    cudaGetSymbolAddress((void**)&p_eb,    g_eb);
    cudaGetSymbolAddress((void**)&p_z,     g_z);
    cudaGetSymbolAddress((void**)&p_core,  g_core);
    cudaGetSymbolAddress((void**)&p_state, g_state);
    cudaGetSymbolAddress((void**)&p_Schk,  g_Schk);
    cudaGetSymbolAddress((void**)&p_u,     g_u);
    cudaGetSymbolAddress((void**)&p_W,     g_W);
    cudaGetSymbolAddress((void**)&p_P,     g_P);
    cudaGetSymbolAddress((void**)&p_Qg,    g_Qg);
    cudaGetSymbolAddress((void**)&p_KcT,   g_KcT);
    cudaGetSymbolAddress((void**)&p_U0,    g_U0);
    cudaGetSymbolAddress((void**)&p_gC,    g_gC);
    cudaGetSymbolAddress((void**)&p_hs,    g_hs_h);
    cudaGetSymbolAddress((void**)&p_Wqkv,  g_Wqkv_h);
    cudaGetSymbolAddress((void**)&p_Wz,    g_Wz_h);
    cudaGetSymbolAddress((void**)&p_Wout,  g_Wout_h);
    cudaGetSymbolAddress((void**)&p_gat,   g_gat_h);

    cudaEventRecord(g_evFork, 0);
    cudaStreamWaitEvent(g_sP, g_evFork, 0);
    cudaStreamWaitEvent(g_sS, g_evFork, 0);
    cudaStreamWaitEvent(g_sT, g_evFork, 0);

    // stream 0: conversions + segmented qkv GEMM + conv/norm
    f2h_kernel<<<(SEQ * HID / 8) / 256, 256>>>(hs, p_hs);
    cudaEventRecord(g_evHs, 0);
    f2h_kernel<<<(CDIM * HID / 8) / 256, 256>>>(Wqkv, p_Wqkv);
    for (int b = 0; b < NSEG; b++) {
        int row0 = b * SEGR;
        hgemm_nt<<<dim3(CDIM / 128, SEGR / 128), 256, HGEMM_SMEM>>>(
            p_hs + (size_t)row0 * HID, p_Wqkv,
            p_mixed + (size_t)row0 * CDIM, SEGR, CDIM, HID);
        conv_norm_seg<<<SEGR, 512>>>(p_mixed, convw, p_qkv, row0);
        cudaEventRecord(g_evQ[b], 0);
    }

    // stream T: ab, z chain, Wout conversion
    ab_kernel<<<(SEQ * NH) / 8, 256, 0, g_sT>>>(hs, Wa, Wb, A_log, dt_bias, p_eb);
    cudaEventRecord(g_evAB, g_sT);
    f2h_kernel<<<(VALD * HID / 8) / 256, 256, 0, g_sT>>>(Wz, p_Wz);
    cudaStreamWaitEvent(g_sT, g_evHs, 0);
    hgemm_nt<<<dim3(VALD / 128, SEQ / 128), 256, HGEMM_SMEM, g_sT>>>(
        p_hs, p_Wz, p_z, SEQ, VALD, HID);
    f2h_kernel<<<(HID * VALD / 8) / 256, 256, 0, g_sT>>>(Wout, p_Wout);

    // stream P: chunk prep per segment
    cudaStreamWaitEvent(g_sP, g_evAB, 0);
    for (int b = 0; b < NSEG; b++) {
        cudaStreamWaitEvent(g_sP, g_evQ[b], 0);
        chunk_prep<<<dim3(CHSEG, NH), 256, PREP_SMEM, g_sP>>>(
            p_qkv, p_eb, p_W, p_P, p_Qg, p_KcT, p_U0, p_gC, b * CHSEG);
        cudaEventRecord(g_evP[b], g_sP);
    }

    // stream S: sequential state recurrence per segment
    for (int b = 0; b < NSEG; b++) {
        cudaStreamWaitEvent(g_sS, g_evP[b], 0);
        chunk_state<<<dim3(8, NH), 256, STATE_SMEM, g_sS>>>(
            p_W, p_KcT, p_U0, p_gC, p_Schk, p_u, p_state, b * CHSEG, CHSEG);
        cudaEventRecord(g_evS[b], g_sS);
    }

    // stream T: parallel O + gate + out GEMM per segment
    for (int b = 0; b < NSEG; b++) {
        int row0 = b * SEGR;
        cudaStreamWaitEvent(g_sT, g_evS[b], 0);
        chunk_out<<<dim3(CHSEG * 8, NH), 256, OUT_SMEM, g_sT>>>(
            p_P, p_Qg, p_Schk, p_u, p_core, b * CHSEG);
        gate_norm_seg<<<(SEGR * NH) / 8, 256, 0, g_sT>>>(
            p_core, p_z, norm_w, p_gat, row0 * NH);
        hgemm_nt<<<dim3(HID / 128, SEGR / 128), 256, HGEMM_SMEM, g_sT>>>(
            p_gat + (size_t)row0 * VALD, p_Wout,
            out + (size_t)row0 * HID, SEGR, HID, VALD);
    }
    cudaEventRecord(g_evEnd, g_sT);
    cudaStreamWaitEvent(0, g_evEnd, 0);
}